// round 8
// baseline (speedup 1.0000x reference)
#include <cuda_runtime.h>
#include <math.h>

#define NN 256
#define MM 1024
#define CC 64
#define KK 16

__device__ float g_xyz[NN*3];
__device__ float g_rf[MM*CC];
__device__ float g_rfi[MM*3];
__device__ float g_wpn[NN*CC];
__device__ float g_rfn[MM*CC];
__device__ float g_sim1[MM*NN];
__device__ float g_sim2[MM*NN];
__device__ float g_invc1[NN], g_invr1[MM], g_invc2[NN], g_invr2[MM];
__device__ int   g_knn[NN*KK];
__device__ float g_pcf[NN*CC];
__device__ float g_imgf[MM*CC];
__device__ float g_pcn[NN*CC];
__device__ float g_imgn[MM*CC];
__device__ float4 g_simQ[NN*MM];
__device__ float g_basem[MM*128];
__device__ float g_basen[NN*128];
__device__ float g_att[NN*CC];
__device__ float g_corres[NN*3];
__device__ float g_win[NN];
__device__ float g_F[NN*MM*CC];      // 64 MB feature buffer
__device__ float g_rmax[NN*MM];

__global__ void prep_kernel(const float* __restrict__ wx, const float* __restrict__ lz,
                            const float* __restrict__ RF3, const float* __restrict__ RF3i){
  int m=blockIdx.x, t=threadIdx.x;
  g_rf[m*CC+t]=RF3[t*MM+m];
  if(t<3) g_rfi[m*3+t]=RF3i[t*MM+m];
  if(m<NN&&t<3) g_xyz[m*3+t]=wx[m*3+t]*lz[m];
}

__global__ void l2norm_kernel(const float* __restrict__ ext,int sel){
  const float* src; float* dst;
  if(sel==0){src=ext;dst=g_wpn;} else if(sel==1){src=g_rf;dst=g_rfn;}
  else if(sel==2){src=g_pcf;dst=g_pcn;} else {src=g_imgf;dst=g_imgn;}
  int r=blockIdx.x,t=threadIdx.x;
  float v=src[r*CC+t], s=v*v;
  for(int o=16;o;o>>=1) s+=__shfl_down_sync(~0u,s,o);
  __shared__ float sh[2];
  if((t&31)==0) sh[t>>5]=s;
  __syncthreads();
  float n=fmaxf(sqrtf(sh[0]+sh[1]),1e-12f);
  dst[r*CC+t]=v/n;
}

__global__ __launch_bounds__(256) void corr_kernel(int sel){
  const float *A,*B; float* S;
  if(sel==0){A=g_rfn;B=g_wpn;S=g_sim1;} else {A=g_imgn;B=g_pcn;S=g_sim2;}
  __shared__ float As[64][65], Bs[64][65];
  int t=threadIdx.x, tx=t&15, ty=t>>4;
  int m0=blockIdx.x*64, n0=blockIdx.y*64;
  #pragma unroll
  for(int i=0;i<16;i++){int idx=t+i*256,r=idx>>6,c=idx&63;
    As[r][c]=A[(m0+r)*CC+c]; Bs[r][c]=B[(n0+r)*CC+c];}
  __syncthreads();
  float acc[4][4];
  #pragma unroll
  for(int i=0;i<4;i++)
    #pragma unroll
    for(int j=0;j<4;j++) acc[i][j]=0.f;
  #pragma unroll 8
  for(int k=0;k<64;k++){
    float a[4],b[4];
    #pragma unroll
    for(int i=0;i<4;i++){a[i]=As[ty*4+i][k]; b[i]=Bs[tx*4+i][k];}
    #pragma unroll
    for(int i=0;i<4;i++)
      #pragma unroll
      for(int j=0;j<4;j++) acc[i][j]+=a[i]*b[j];
  }
  #pragma unroll
  for(int i=0;i<4;i++)
    #pragma unroll
    for(int j=0;j<4;j++) S[(m0+ty*4+i)*NN+n0+tx*4+j]=acc[i][j];
}

__global__ void colmax_kernel(int sel){
  const float* S=sel?g_sim2:g_sim1; float* ic=sel?g_invc2:g_invc1;
  int n=blockIdx.x, t=threadIdx.x;
  float mx=-1e30f;
  for(int m=t;m<MM;m+=128) mx=fmaxf(mx,S[m*NN+n]);
  for(int o=16;o;o>>=1) mx=fmaxf(mx,__shfl_down_sync(~0u,mx,o));
  __shared__ float sh[4];
  if((t&31)==0) sh[t>>5]=mx;
  __syncthreads();
  if(t==0){
    mx=fmaxf(fmaxf(sh[0],sh[1]),fmaxf(sh[2],sh[3]));
    ic[n]=1.f/(mx+1e-6f);
  }
}
__global__ void rowmax_kernel(int sel){
  const float* S=sel?g_sim2:g_sim1; float* ir=sel?g_invr2:g_invr1;
  int w=threadIdx.x>>5,l=threadIdx.x&31,m=blockIdx.x*8+w;
  float mx=-1e30f;
  for(int n=l;n<NN;n+=32) mx=fmaxf(mx,S[m*NN+n]);
  for(int o=16;o;o>>=1) mx=fmaxf(mx,__shfl_down_sync(~0u,mx,o));
  if(l==0) ir[m]=1.f/(mx+1e-10f);
}

__global__ void knn_kernel(){
  int n=blockIdx.x,t=threadIdx.x;
  __shared__ float sx[NN*3], d2[NN], wm[8];
  __shared__ int wi[8];
  for(int i=t;i<NN*3;i+=256) sx[i]=g_xyz[i];
  __syncthreads();
  float cx=sx[n*3],cy=sx[n*3+1],cz=sx[n*3+2];
  float dx=sx[t*3]-cx,dy=sx[t*3+1]-cy,dz=sx[t*3+2]-cz;
  d2[t]=dx*dx+dy*dy+dz*dz;
  __syncthreads();
  for(int it=0;it<KK;it++){
    float v=d2[t]; int id=t;
    for(int o=16;o;o>>=1){
      float ov=__shfl_down_sync(~0u,v,o); int oi=__shfl_down_sync(~0u,id,o);
      if(ov<v||(ov==v&&oi<id)){v=ov;id=oi;}
    }
    if((t&31)==0){wm[t>>5]=v;wi[t>>5]=id;}
    __syncthreads();
    if(t==0){
      float bv=wm[0];int bi=wi[0];
      for(int w=1;w<8;w++) if(wm[w]<bv||(wm[w]==bv&&wi[w]<bi)){bv=wm[w];bi=wi[w];}
      g_knn[n*KK+it]=bi; d2[bi]=1e38f;
    }
    __syncthreads();
  }
}

#define MLP2_SMEM (15888*4)
__global__ __launch_bounds__(256) void mlp2_kernel(const float* __restrict__ wp,
    const float* __restrict__ w0,const float* __restrict__ b0,
    const float* __restrict__ w1,const float* __restrict__ b1,
    const float* __restrict__ w2,const float* __restrict__ b2){
  extern __shared__ float sm[];
  float* W0=sm; float* W1=W0+4352; float* W2=W1+4096;
  float* B0=W2+4096; float* B1=B0+64; float* B2=B1+64;
  float* IN=B2+64; float* Ha=IN+1088; float* Hb=Ha+1024; float* wk=Hb+1024;
  int n=blockIdx.x,t=threadIdx.x;
  for(int i=t;i<4352;i+=256) W0[i]=w0[i];
  for(int i=t;i<4096;i+=256){W1[i]=w1[i];W2[i]=w2[i];}
  if(t<64){B0[t]=b0[t];B1[t]=b1[t];B2[t]=b2[t];}
  for(int i=t;i<16*68;i+=256){
    int k=i/68,f=i%68,nb=g_knn[n*KK+k]; float val;
    if(f<64) val=wp[nb*CC+f];
    else if(f<67) val=g_xyz[nb*3+(f-64)]-g_xyz[n*3+(f-64)];
    else{
      float dx=g_xyz[nb*3]-g_xyz[n*3],dy=g_xyz[nb*3+1]-g_xyz[n*3+1],dz=g_xyz[nb*3+2]-g_xyz[n*3+2];
      val=sqrtf(dx*dx+dy*dy+dz*dz);
    }
    IN[k*68+f]=val;
  }
  __syncthreads();
  for(int o=t;o<1024;o+=256){int k=o>>6,j=o&63; float s=B0[j];
    #pragma unroll 4
    for(int i=0;i<68;i++) s+=IN[k*68+i]*W0[i*64+j];
    Ha[o]=fmaxf(s,0.f);}
  __syncthreads();
  for(int o=t;o<1024;o+=256){int k=o>>6,j=o&63; float s=B1[j];
    #pragma unroll 4
    for(int i=0;i<64;i++) s+=Ha[k*64+i]*W1[i*64+j];
    Hb[o]=fmaxf(s,0.f);}
  __syncthreads();
  for(int o=t;o<1024;o+=256){int k=o>>6,j=o&63; float s=B2[j];
    #pragma unroll 4
    for(int i=0;i<64;i++) s+=Hb[k*64+i]*W2[i*64+j];
    Ha[o]=fmaxf(s,0.f);}
  __syncthreads();
  if(t<16){float mx=-1e30f; for(int j=0;j<64;j++) mx=fmaxf(mx,Ha[t*64+j]); wk[t]=mx;}
  __syncthreads();
  if(t==0){
    float mx=-1e30f; for(int k=0;k<16;k++) mx=fmaxf(mx,wk[k]);
    float s=0.f; for(int k=0;k<16;k++){wk[k]=expf(wk[k]-mx);s+=wk[k];}
    float inv=1.f/s; for(int k=0;k<16;k++) wk[k]*=inv;
  }
  __syncthreads();
  if(t<64){float s=0.f; for(int k=0;k<16;k++) s+=wk[k]*IN[k*68+t]; g_pcf[n*CC+t]=s;}
}

#define MLP3_SMEM (14443*4)
__global__ __launch_bounds__(256) void mlp3_kernel(
    const float* __restrict__ w0,const float* __restrict__ b0,
    const float* __restrict__ w1,const float* __restrict__ b1,
    const float* __restrict__ w2,const float* __restrict__ b2){
  extern __shared__ float sm[];
  float* W0=sm; float* W1=W0+4288; float* W2=W1+4096;
  float* B0=W2+4096; float* B1=B0+64; float* B2=B1+64;
  float* IN=B2+64; float* Ha=IN+603; float* Hb=Ha+576; float* wk=Hb+576;
  int m=blockIdx.x,t=threadIdx.x,y=m>>5,x=m&31;
  for(int i=t;i<4288;i+=256) W0[i]=w0[i];
  for(int i=t;i<4096;i+=256){W1[i]=w1[i];W2[i]=w2[i];}
  if(t<64){B0[t]=b0[t];B1[t]=b1[t];B2[t]=b2[t];}
  for(int i=t;i<9*67;i+=256){
    int k=i/67,f=i%67,dy=k/3-1,dx=k%3-1,yy=y+dy,xx=x+dx;
    float val=0.f;
    if(yy>=0&&yy<32&&xx>=0&&xx<32){int mm=yy*32+xx; val=(f<3)?g_rfi[mm*3+f]:g_rf[mm*CC+f-3];}
    IN[k*67+f]=val;
  }
  __syncthreads();
  for(int o=t;o<576;o+=256){int k=o>>6,j=o&63; float s=B0[j];
    #pragma unroll 4
    for(int i=0;i<67;i++) s+=IN[k*67+i]*W0[i*64+j];
    Ha[o]=fmaxf(s,0.f);}
  __syncthreads();
  for(int o=t;o<576;o+=256){int k=o>>6,j=o&63; float s=B1[j];
    #pragma unroll 4
    for(int i=0;i<64;i++) s+=Ha[k*64+i]*W1[i*64+j];
    Hb[o]=fmaxf(s,0.f);}
  __syncthreads();
  for(int o=t;o<576;o+=256){int k=o>>6,j=o&63; float s=B2[j];
    #pragma unroll 4
    for(int i=0;i<64;i++) s+=Hb[k*64+i]*W2[i*64+j];
    Ha[o]=fmaxf(s,0.f);}
  __syncthreads();
  if(t<9){float mx=-1e30f; for(int j=0;j<64;j++) mx=fmaxf(mx,Ha[t*64+j]); wk[t]=mx;}
  __syncthreads();
  if(t==0){
    float mx=-1e30f; for(int k=0;k<9;k++) mx=fmaxf(mx,wk[k]);
    float s=0.f; for(int k=0;k<9;k++){wk[k]=expf(wk[k]-mx);s+=wk[k];}
    float inv=1.f/s; for(int k=0;k<9;k++) wk[k]*=inv;
  }
  __syncthreads();
  if(t<64){float s=0.f; for(int k=0;k<9;k++) s+=wk[k]*IN[k*67+3+t]; g_imgf[m*CC+t]=s;}
}

__global__ void pack_kernel(){
  int m=blockIdx.x, n=threadIdx.x;
  float s1=g_sim1[m*NN+n], s2=g_sim2[m*NN+n];
  float4 q; q.x=s1*g_invc1[n]; q.y=s1*g_invr1[m]; q.z=s2*g_invc2[n]; q.w=s2*g_invr2[m];
  g_simQ[n*MM+m]=q;
}

__global__ void basem_kernel(const float* __restrict__ w1_0,const float* __restrict__ b1_0){
  int m=blockIdx.x,t=threadIdx.x;
  __shared__ float in[67];
  if(t<3) in[t]=g_rfi[m*3+t]; else if(t<67) in[t]=g_rf[m*CC+t-3];
  __syncthreads();
  float acc=b1_0[t];
  #pragma unroll
  for(int i=0;i<3;i++) acc+=in[i]*w1_0[(3+i)*128+t];
  #pragma unroll 4
  for(int i=0;i<64;i++) acc+=in[3+i]*w1_0[(70+i)*128+t];
  g_basem[m*128+t]=acc;
}
__global__ void basen_kernel(const float* __restrict__ wp,const float* __restrict__ w1_0){
  int n=blockIdx.x,t=threadIdx.x;
  __shared__ float in[67];
  if(t<3) in[t]=g_xyz[n*3+t]; else if(t<67) in[t]=wp[n*CC+t-3];
  __syncthreads();
  float acc=0.f;
  #pragma unroll
  for(int i=0;i<3;i++) acc+=in[i]*w1_0[i*128+t];
  #pragma unroll 4
  for(int i=0;i<64;i++) acc+=in[3+i]*w1_0[(6+i)*128+t];
  g_basen[n*128+t]=acc;
}

// ---------------- pass 1: feats GEMM (high occupancy, f32x2) ----------------
#define PACK2(d,x) asm("mov.b64 %0,{%1,%1};":"=l"(d):"r"(__float_as_uint(x)))
#define FMA2(d,a,b) asm("fma.rn.f32x2 %0,%1,%2,%0;":"+l"(d):"l"(a),"l"(b))
#define UNPK(a,d0,d1) { unsigned int _lo,_hi; asm("mov.b64 {%0,%1},%2;":"=r"(_lo),"=r"(_hi):"l"(a)); d0=__uint_as_float(_lo); d1=__uint_as_float(_hi); }

#define FT_WA 0
#define FT_WB 8192
#define FT_BA 12288
#define FT_BB 12352
#define FT_WS 12416
#define FT_BN 12928
#define FT_H1 13056
#define FT_H2 21312
#define FT_SMEM (25664*4)

__global__ __launch_bounds__(256,2) void feat_kernel(
    const float* __restrict__ w1_0,const float* __restrict__ w1_1,const float* __restrict__ b1_1,
    const float* __restrict__ w1_2,const float* __restrict__ b1_2){
  extern __shared__ float sm[];
  float* WA=sm+FT_WA; float* WB=sm+FT_WB; float* BA=sm+FT_BA; float* BB=sm+FT_BB;
  float* WS=sm+FT_WS; float* BN=sm+FT_BN; float* H1=sm+FT_H1; float* H2=sm+FT_H2;
  int t=threadIdx.x, mt=blockIdx.x, n=blockIdx.y, m0=mt*64;
  for(int i=t;i<8192;i+=256) WA[i]=w1_1[i];
  for(int i=t;i<4096;i+=256) WB[i]=w1_2[i];
  if(t<64){BA[t]=b1_1[t];BB[t]=b1_2[t];}
  else if(t>=64&&t<192) BN[t-64]=g_basen[n*128+(t-64)];
  for(int i=t;i<512;i+=256) WS[i]=w1_0[134*128+i];
  for(int idx=t;idx<8192;idx+=256){int mr=idx>>7,c=idx&127; H1[mr*129+c]=g_basem[(m0+mr)*128+c];}
  __syncthreads();
  { // phase A: H1 = relu(basem + basen + sim4 @ WS)
    int mloc=t&63,q=t>>6;
    float4 s4=g_simQ[n*MM+m0+mloc];
    #pragma unroll
    for(int i=0;i<32;i++){
      int c=q*32+i;
      float h=H1[mloc*129+c]+BN[c]+s4.x*WS[c]+s4.y*WS[128+c]+s4.z*WS[256+c]+s4.w*WS[384+c];
      H1[mloc*129+c]=fmaxf(h,0.f);
    }
  }
  __syncthreads();
  int r0=(t>>3)*2, j0=(t&7)*8;
  unsigned long long a0[4],a1[4];
  // phase B: H2 = relu(H1 @ WA + BA)   (64x128 @ 128x64)
  #pragma unroll
  for(int i=0;i<4;i++){ a0[i]=*(const unsigned long long*)&BA[j0+2*i]; a1[i]=a0[i]; }
  #pragma unroll 4
  for(int k=0;k<128;k++){
    unsigned long long p0,p1;
    PACK2(p0,H1[r0*129+k]); PACK2(p1,H1[(r0+1)*129+k]);
    ulonglong2 wv0=*(const ulonglong2*)&WA[k*64+j0];
    ulonglong2 wv1=*(const ulonglong2*)&WA[k*64+j0+4];
    FMA2(a0[0],p0,wv0.x); FMA2(a0[1],p0,wv0.y); FMA2(a0[2],p0,wv1.x); FMA2(a0[3],p0,wv1.y);
    FMA2(a1[0],p1,wv0.x); FMA2(a1[1],p1,wv0.y); FMA2(a1[2],p1,wv1.x); FMA2(a1[3],p1,wv1.y);
  }
  #pragma unroll
  for(int i=0;i<4;i++){
    float x0,x1;
    UNPK(a0[i],x0,x1);
    H2[r0*68+j0+2*i]=fmaxf(x0,0.f); H2[r0*68+j0+2*i+1]=fmaxf(x1,0.f);
    UNPK(a1[i],x0,x1);
    H2[(r0+1)*68+j0+2*i]=fmaxf(x0,0.f); H2[(r0+1)*68+j0+2*i+1]=fmaxf(x1,0.f);
  }
  __syncthreads();
  // phase C: F = relu(H2 @ WB + BB)   (64x64 @ 64x64)
  #pragma unroll
  for(int i=0;i<4;i++){ a0[i]=*(const unsigned long long*)&BB[j0+2*i]; a1[i]=a0[i]; }
  #pragma unroll 4
  for(int k=0;k<64;k++){
    unsigned long long p0,p1;
    PACK2(p0,H2[r0*68+k]); PACK2(p1,H2[(r0+1)*68+k]);
    ulonglong2 wv0=*(const ulonglong2*)&WB[k*64+j0];
    ulonglong2 wv1=*(const ulonglong2*)&WB[k*64+j0+4];
    FMA2(a0[0],p0,wv0.x); FMA2(a0[1],p0,wv0.y); FMA2(a0[2],p0,wv1.x); FMA2(a0[3],p0,wv1.y);
    FMA2(a1[0],p1,wv0.x); FMA2(a1[1],p1,wv0.y); FMA2(a1[2],p1,wv1.x); FMA2(a1[3],p1,wv1.y);
  }
  float* F=H1;  // reuse H1 region (dead after phase B); pitch 68
  #pragma unroll
  for(int i=0;i<4;i++){
    float x0,x1;
    UNPK(a0[i],x0,x1);
    F[r0*68+j0+2*i]=fmaxf(x0,0.f); F[r0*68+j0+2*i+1]=fmaxf(x1,0.f);
    UNPK(a1[i],x0,x1);
    F[(r0+1)*68+j0+2*i]=fmaxf(x0,0.f); F[(r0+1)*68+j0+2*i+1]=fmaxf(x1,0.f);
  }
  __syncthreads();
  if(t<64){
    float mx=-1e30f;
    #pragma unroll 8
    for(int c=0;c<64;c++) mx=fmaxf(mx,F[t*68+c]);
    g_rmax[n*MM+m0+t]=mx;
  }
  for(int idx=t;idx<4096;idx+=256){
    int mr=idx>>6,c=idx&63;
    g_F[(n*MM+m0+mr)*64+c]=F[mr*68+c];
  }
}

// ---------------- pass 2: softmax reduce -> att, corres ----------------
__global__ __launch_bounds__(256) void reduce_kernel(){
  int n=blockIdx.x, t=threadIdx.x;
  __shared__ float ee[MM];
  __shared__ float red[256];
  float mx=-1e30f;
  for(int m=t;m<MM;m+=256){ float v=g_rmax[n*MM+m]; ee[m]=v; mx=fmaxf(mx,v); }
  red[t]=mx; __syncthreads();
  for(int s=128;s;s>>=1){ if(t<s) red[t]=fmaxf(red[t],red[t+s]); __syncthreads(); }
  float gmax=red[0]; __syncthreads();
  float zs=0.f;
  for(int m=t;m<MM;m+=256){ float e=expf(ee[m]-gmax); ee[m]=e; zs+=e; }
  red[t]=zs; __syncthreads();
  for(int s=128;s;s>>=1){ if(t<s) red[t]+=red[t+s]; __syncthreads(); }
  float z=red[0]; __syncthreads();
  int c=t&63, ch=t>>6;
  const float* Fn=g_F+n*MM*64;
  float acc=0.f;
  #pragma unroll 4
  for(int m=ch*256;m<ch*256+256;m++) acc+=ee[m]*Fn[m*64+c];
  red[t]=acc; __syncthreads();
  if(t<64) g_att[n*CC+t]=(red[t]+red[64+t]+red[128+t]+red[192+t])/z;
  if(t<96){
    int cc=t>>5, l=t&31; float a=0.f;
    for(int m=l;m<MM;m+=32) a+=ee[m]*g_rfi[m*3+cc];
    for(int o=16;o;o>>=1) a+=__shfl_down_sync(~0u,a,o);
    if(l==0) g_corres[n*3+cc]=a/z;
  }
}

__global__ void head_kernel(const float* __restrict__ wm0,const float* __restrict__ bm0,
    const float* __restrict__ wm1,const float* __restrict__ bm1,
    const float* __restrict__ wm2,const float* __restrict__ bm2,float* __restrict__ outw){
  int n=blockIdx.x,t=threadIdx.x;
  __shared__ float a[64],h1[64],h2[128];
  if(t<64) a[t]=g_att[n*CC+t];
  __syncthreads();
  if(t<64){
    float s=bm0[t];
    #pragma unroll 4
    for(int k=0;k<64;k++) s+=a[k]*wm0[k*64+t];
    h1[t]=fmaxf(s,0.f);
  }
  __syncthreads();
  {
    float s=bm1[t];
    #pragma unroll 4
    for(int k=0;k<64;k++) s+=h1[k]*wm1[k*128+t];
    h2[t]=fmaxf(s,0.f);
  }
  __syncthreads();
  if(t==0){
    float l0=bm2[0],l1=bm2[1];
    for(int k=0;k<128;k++){l0+=h2[k]*wm2[k*2];l1+=h2[k]*wm2[k*2+1];}
    float mx=fmaxf(l0,l1),e0=expf(l0-mx),e1=expf(l1-mx),inv=1.f/(e0+e1);
    outw[n*2]=e0*inv; outw[n*2+1]=e1*inv;
    g_win[n]=(l1>l0)?1.f:0.f;
  }
}

__device__ float brs(float v,float* red){
  int t=threadIdx.x;
  red[t]=v; __syncthreads();
  for(int s=128;s>0;s>>=1){ if(t<s) red[t]+=red[t+s]; __syncthreads(); }
  float r=red[0]; __syncthreads();
  return r;
}

__global__ void pnp_kernel(float* __restrict__ out){
  __shared__ float red[256];
  int t=threadIdx.x;
  float w=g_win[t];
  float sx=g_xyz[t*3],sy=g_xyz[t*3+1],sz=g_xyz[t*3+2];
  float u=g_corres[t*3],v=g_corres[t*3+1];
  float dx=u*sz,dy=v*sz,dz=sz;
  float sw=brs(w,red);
  float wn=w/(sw+1e-8f);
  float scx=brs(wn*sx,red),scy=brs(wn*sy,red),scz=brs(wn*sz,red);
  float dcx=brs(wn*dx,red),dcy=brs(wn*dy,red),dcz=brs(wn*dz,red);
  float ax=sx-scx,ay=sy-scy,az=sz-scz;
  float bx=dx-dcx,by=dy-dcy,bz=dz-dcz;
  float hm[9];
  hm[0]=brs(wn*ax*bx,red);hm[1]=brs(wn*ax*by,red);hm[2]=brs(wn*ax*bz,red);
  hm[3]=brs(wn*ay*bx,red);hm[4]=brs(wn*ay*by,red);hm[5]=brs(wn*ay*bz,red);
  hm[6]=brs(wn*az*bx,red);hm[7]=brs(wn*az*by,red);hm[8]=brs(wn*az*bz,red);
  if(t==0){
    double h[3][3]={{hm[0],hm[1],hm[2]},{hm[3],hm[4],hm[5]},{hm[6],hm[7],hm[8]}};
    double A[3][3],V[3][3]={{1,0,0},{0,1,0},{0,0,1}};
    for(int i=0;i<3;i++)for(int j=0;j<3;j++){double s=0;for(int k=0;k<3;k++)s+=h[k][i]*h[k][j];A[i][j]=s;}
    const int P[3]={0,0,1},Q[3]={1,2,2};
    for(int sweep=0;sweep<20;sweep++)
      for(int r=0;r<3;r++){
        int p=P[r],qq=Q[r];
        double apq=A[p][qq];
        if(fabs(apq)<1e-300) continue;
        double tau=(A[qq][qq]-A[p][p])/(2.0*apq);
        double tt=((tau>=0)?1.0:-1.0)/(fabs(tau)+sqrt(1.0+tau*tau));
        double c=1.0/sqrt(1.0+tt*tt),s=tt*c;
        for(int k=0;k<3;k++){double a1=A[k][p],a2=A[k][qq];A[k][p]=c*a1-s*a2;A[k][qq]=s*a1+c*a2;}
        for(int k=0;k<3;k++){double a1=A[p][k],a2=A[qq][k];A[p][k]=c*a1-s*a2;A[qq][k]=s*a1+c*a2;}
        for(int k=0;k<3;k++){double v1=V[k][p],v2=V[k][qq];V[k][p]=c*v1-s*v2;V[k][qq]=s*v1+c*v2;}
      }
    double lam[3]={A[0][0],A[1][1],A[2][2]};
    int o[3]={0,1,2};
    if(lam[o[0]]<lam[o[1]]){int x=o[0];o[0]=o[1];o[1]=x;}
    if(lam[o[1]]<lam[o[2]]){int x=o[1];o[1]=o[2];o[2]=x;}
    if(lam[o[0]]<lam[o[1]]){int x=o[0];o[0]=o[1];o[1]=x;}
    double vv[3][3],uu[3][3],sg[3];
    for(int i=0;i<3;i++){
      sg[i]=sqrt(fmax(lam[o[i]],0.0));
      for(int k=0;k<3;k++) vv[i][k]=V[k][o[i]];
    }
    for(int i=0;i<2;i++){
      for(int j=0;j<3;j++){double s=0;for(int k=0;k<3;k++)s+=h[j][k]*vv[i][k];uu[i][j]=s/fmax(sg[i],1e-300);}
    }
    if(sg[2]>1e-9*sg[0]){
      for(int j=0;j<3;j++){double s=0;for(int k=0;k<3;k++)s+=h[j][k]*vv[2][k];uu[2][j]=s/sg[2];}
    } else {
      uu[2][0]=uu[0][1]*uu[1][2]-uu[0][2]*uu[1][1];
      uu[2][1]=uu[0][2]*uu[1][0]-uu[0][0]*uu[1][2];
      uu[2][2]=uu[0][0]*uu[1][1]-uu[0][1]*uu[1][0];
    }
    double detV=vv[0][0]*(vv[1][1]*vv[2][2]-vv[1][2]*vv[2][1])
               -vv[0][1]*(vv[1][0]*vv[2][2]-vv[1][2]*vv[2][0])
               +vv[0][2]*(vv[1][0]*vv[2][1]-vv[1][1]*vv[2][0]);
    double detU=uu[0][0]*(uu[1][1]*uu[2][2]-uu[1][2]*uu[2][1])
               -uu[0][1]*(uu[1][0]*uu[2][2]-uu[1][2]*uu[2][0])
               +uu[0][2]*(uu[1][0]*uu[2][1]-uu[1][1]*uu[2][0]);
    double d=detV*detU;
    double R[3][3];
    for(int i=0;i<3;i++)for(int j=0;j<3;j++)
      R[i][j]=vv[0][i]*uu[0][j]+vv[1][i]*uu[1][j]+d*vv[2][i]*uu[2][j];
    double sc[3]={scx,scy,scz},dc[3]={dcx,dcy,dcz};
    for(int i=0;i<3;i++){
      for(int j=0;j<3;j++) out[i*3+j]=(float)R[i][j];
      double s=0; for(int j=0;j<3;j++) s+=R[i][j]*sc[j];
      out[9+i]=(float)(dc[i]-s);
    }
  }
}

extern "C" void kernel_launch(void* const* d_in, const int* in_sizes, int n_in,
                              void* d_out, int out_size){
  const float* wx  =(const float*)d_in[0];
  const float* wp  =(const float*)d_in[1];
  const float* RF3 =(const float*)d_in[2];
  const float* RF3i=(const float*)d_in[3];
  const float* lz  =(const float*)d_in[4];
  const float* w2_0=(const float*)d_in[5];  const float* b2_0=(const float*)d_in[6];
  const float* w2_1=(const float*)d_in[7];  const float* b2_1=(const float*)d_in[8];
  const float* w2_2=(const float*)d_in[9];  const float* b2_2=(const float*)d_in[10];
  const float* w3_0=(const float*)d_in[11]; const float* b3_0=(const float*)d_in[12];
  const float* w3_1=(const float*)d_in[13]; const float* b3_1=(const float*)d_in[14];
  const float* w3_2=(const float*)d_in[15]; const float* b3_2=(const float*)d_in[16];
  const float* w1_0=(const float*)d_in[17]; const float* b1_0=(const float*)d_in[18];
  const float* w1_1=(const float*)d_in[19]; const float* b1_1=(const float*)d_in[20];
  const float* w1_2=(const float*)d_in[21]; const float* b1_2=(const float*)d_in[22];
  const float* wm_0=(const float*)d_in[23]; const float* bm_0=(const float*)d_in[24];
  const float* wm_1=(const float*)d_in[25]; const float* bm_1=(const float*)d_in[26];
  const float* wm_2=(const float*)d_in[27]; const float* bm_2=(const float*)d_in[28];
  float* out=(float*)d_out;

  cudaFuncSetAttribute(mlp2_kernel, cudaFuncAttributeMaxDynamicSharedMemorySize, MLP2_SMEM);
  cudaFuncSetAttribute(mlp3_kernel, cudaFuncAttributeMaxDynamicSharedMemorySize, MLP3_SMEM);
  cudaFuncSetAttribute(feat_kernel, cudaFuncAttributeMaxDynamicSharedMemorySize, FT_SMEM);

  prep_kernel<<<MM,64>>>(wx,lz,RF3,RF3i);
  l2norm_kernel<<<NN,64>>>(wp,0);
  l2norm_kernel<<<MM,64>>>(nullptr,1);
  corr_kernel<<<dim3(MM/64,NN/64),256>>>(0);
  colmax_kernel<<<NN,128>>>(0);
  rowmax_kernel<<<MM/8,256>>>(0);
  knn_kernel<<<NN,256>>>();
  mlp2_kernel<<<NN,256,MLP2_SMEM>>>(wp,w2_0,b2_0,w2_1,b2_1,w2_2,b2_2);
  mlp3_kernel<<<MM,256,MLP3_SMEM>>>(w3_0,b3_0,w3_1,b3_1,w3_2,b3_2);
  l2norm_kernel<<<NN,64>>>(nullptr,2);
  l2norm_kernel<<<MM,64>>>(nullptr,3);
  corr_kernel<<<dim3(MM/64,NN/64),256>>>(1);
  colmax_kernel<<<NN,128>>>(1);
  rowmax_kernel<<<MM/8,256>>>(1);
  pack_kernel<<<MM,NN>>>();
  basem_kernel<<<MM,128>>>(w1_0,b1_0);
  basen_kernel<<<NN,128>>>(wp,w1_0);
  feat_kernel<<<dim3(MM/64,NN),256,FT_SMEM>>>(w1_0,w1_1,b1_1,w1_2,b1_2);
  reduce_kernel<<<NN,256>>>();
  head_kernel<<<NN,128>>>(wm_0,bm_0,wm_1,bm_1,wm_2,bm_2,out+12);
  pnp_kernel<<<1,NN>>>(out);
}

// round 12
// speedup vs baseline: 1.0767x; 1.0767x over previous
#include <cuda_runtime.h>
#include <math.h>

#define NN 256
#define MM 1024
#define CC 64
#define KK 16

__device__ float g_xyz[NN*3];
__device__ float g_rf[MM*CC];
__device__ float g_rfi[MM*3];
__device__ float g_wpn[NN*CC];
__device__ float g_rfn[MM*CC];
__device__ float g_sim1[MM*NN];
__device__ float g_sim2[MM*NN];
__device__ float g_invc1[NN], g_invr1[MM], g_invc2[NN], g_invr2[MM];
__device__ int   g_knn[NN*KK];
__device__ float g_pcf[NN*CC];
__device__ float g_imgf[MM*CC];
__device__ float g_pcn[NN*CC];
__device__ float g_imgn[MM*CC];
__device__ float4 g_simQ[NN*MM];
__device__ float g_basem[MM*128];
__device__ float g_basen[NN*128];
__device__ float g_att[NN*CC];
__device__ float g_corres[NN*3];
__device__ float g_win[NN];

__global__ void prep_kernel(const float* __restrict__ wx, const float* __restrict__ lz,
                            const float* __restrict__ RF3, const float* __restrict__ RF3i){
  int m=blockIdx.x, t=threadIdx.x;
  g_rf[m*CC+t]=RF3[t*MM+m];
  if(t<3) g_rfi[m*3+t]=RF3i[t*MM+m];
  if(m<NN&&t<3) g_xyz[m*3+t]=wx[m*3+t]*lz[m];
}

__global__ void l2norm_kernel(const float* __restrict__ ext,int sel){
  const float* src; float* dst;
  if(sel==0){src=ext;dst=g_wpn;} else if(sel==1){src=g_rf;dst=g_rfn;}
  else if(sel==2){src=g_pcf;dst=g_pcn;} else {src=g_imgf;dst=g_imgn;}
  int r=blockIdx.x,t=threadIdx.x;
  float v=src[r*CC+t], s=v*v;
  for(int o=16;o;o>>=1) s+=__shfl_down_sync(~0u,s,o);
  __shared__ float sh[2];
  if((t&31)==0) sh[t>>5]=s;
  __syncthreads();
  float n=fmaxf(sqrtf(sh[0]+sh[1]),1e-12f);
  dst[r*CC+t]=v/n;
}

__global__ __launch_bounds__(256) void corr_kernel(int sel){
  const float *A,*B; float* S;
  if(sel==0){A=g_rfn;B=g_wpn;S=g_sim1;} else {A=g_imgn;B=g_pcn;S=g_sim2;}
  __shared__ float As[64][65], Bs[64][65];
  int t=threadIdx.x, tx=t&15, ty=t>>4;
  int m0=blockIdx.x*64, n0=blockIdx.y*64;
  #pragma unroll
  for(int i=0;i<16;i++){int idx=t+i*256,r=idx>>6,c=idx&63;
    As[r][c]=A[(m0+r)*CC+c]; Bs[r][c]=B[(n0+r)*CC+c];}
  __syncthreads();
  float acc[4][4];
  #pragma unroll
  for(int i=0;i<4;i++)
    #pragma unroll
    for(int j=0;j<4;j++) acc[i][j]=0.f;
  #pragma unroll 8
  for(int k=0;k<64;k++){
    float a[4],b[4];
    #pragma unroll
    for(int i=0;i<4;i++){a[i]=As[ty*4+i][k]; b[i]=Bs[tx*4+i][k];}
    #pragma unroll
    for(int i=0;i<4;i++)
      #pragma unroll
      for(int j=0;j<4;j++) acc[i][j]+=a[i]*b[j];
  }
  #pragma unroll
  for(int i=0;i<4;i++)
    #pragma unroll
    for(int j=0;j<4;j++) S[(m0+ty*4+i)*NN+n0+tx*4+j]=acc[i][j];
}

__global__ void colmax_kernel(int sel){
  const float* S=sel?g_sim2:g_sim1; float* ic=sel?g_invc2:g_invc1;
  int n=blockIdx.x, t=threadIdx.x;
  float mx=-1e30f;
  for(int m=t;m<MM;m+=128) mx=fmaxf(mx,S[m*NN+n]);
  for(int o=16;o;o>>=1) mx=fmaxf(mx,__shfl_down_sync(~0u,mx,o));
  __shared__ float sh[4];
  if((t&31)==0) sh[t>>5]=mx;
  __syncthreads();
  if(t==0){
    mx=fmaxf(fmaxf(sh[0],sh[1]),fmaxf(sh[2],sh[3]));
    ic[n]=1.f/(mx+1e-6f);
  }
}
__global__ void rowmax_kernel(int sel){
  const float* S=sel?g_sim2:g_sim1; float* ir=sel?g_invr2:g_invr1;
  int w=threadIdx.x>>5,l=threadIdx.x&31,m=blockIdx.x*8+w;
  float mx=-1e30f;
  for(int n=l;n<NN;n+=32) mx=fmaxf(mx,S[m*NN+n]);
  for(int o=16;o;o>>=1) mx=fmaxf(mx,__shfl_down_sync(~0u,mx,o));
  if(l==0) ir[m]=1.f/(mx+1e-10f);
}

__global__ void knn_kernel(){
  int n=blockIdx.x,t=threadIdx.x;
  __shared__ float sx[NN*3], d2[NN], wm[8];
  __shared__ int wi[8];
  for(int i=t;i<NN*3;i+=256) sx[i]=g_xyz[i];
  __syncthreads();
  float cx=sx[n*3],cy=sx[n*3+1],cz=sx[n*3+2];
  float dx=sx[t*3]-cx,dy=sx[t*3+1]-cy,dz=sx[t*3+2]-cz;
  d2[t]=dx*dx+dy*dy+dz*dz;
  __syncthreads();
  for(int it=0;it<KK;it++){
    float v=d2[t]; int id=t;
    for(int o=16;o;o>>=1){
      float ov=__shfl_down_sync(~0u,v,o); int oi=__shfl_down_sync(~0u,id,o);
      if(ov<v||(ov==v&&oi<id)){v=ov;id=oi;}
    }
    if((t&31)==0){wm[t>>5]=v;wi[t>>5]=id;}
    __syncthreads();
    if(t==0){
      float bv=wm[0];int bi=wi[0];
      for(int w=1;w<8;w++) if(wm[w]<bv||(wm[w]==bv&&wi[w]<bi)){bv=wm[w];bi=wi[w];}
      g_knn[n*KK+it]=bi; d2[bi]=1e38f;
    }
    __syncthreads();
  }
}

#define MLP2_SMEM (15888*4)
__global__ __launch_bounds__(256) void mlp2_kernel(const float* __restrict__ wp,
    const float* __restrict__ w0,const float* __restrict__ b0,
    const float* __restrict__ w1,const float* __restrict__ b1,
    const float* __restrict__ w2,const float* __restrict__ b2){
  extern __shared__ float sm[];
  float* W0=sm; float* W1=W0+4352; float* W2=W1+4096;
  float* B0=W2+4096; float* B1=B0+64; float* B2=B1+64;
  float* IN=B2+64; float* Ha=IN+1088; float* Hb=Ha+1024; float* wk=Hb+1024;
  int n=blockIdx.x,t=threadIdx.x;
  for(int i=t;i<4352;i+=256) W0[i]=w0[i];
  for(int i=t;i<4096;i+=256){W1[i]=w1[i];W2[i]=w2[i];}
  if(t<64){B0[t]=b0[t];B1[t]=b1[t];B2[t]=b2[t];}
  for(int i=t;i<16*68;i+=256){
    int k=i/68,f=i%68,nb=g_knn[n*KK+k]; float val;
    if(f<64) val=wp[nb*CC+f];
    else if(f<67) val=g_xyz[nb*3+(f-64)]-g_xyz[n*3+(f-64)];
    else{
      float dx=g_xyz[nb*3]-g_xyz[n*3],dy=g_xyz[nb*3+1]-g_xyz[n*3+1],dz=g_xyz[nb*3+2]-g_xyz[n*3+2];
      val=sqrtf(dx*dx+dy*dy+dz*dz);
    }
    IN[k*68+f]=val;
  }
  __syncthreads();
  for(int o=t;o<1024;o+=256){int k=o>>6,j=o&63; float s=B0[j];
    #pragma unroll 4
    for(int i=0;i<68;i++) s+=IN[k*68+i]*W0[i*64+j];
    Ha[o]=fmaxf(s,0.f);}
  __syncthreads();
  for(int o=t;o<1024;o+=256){int k=o>>6,j=o&63; float s=B1[j];
    #pragma unroll 4
    for(int i=0;i<64;i++) s+=Ha[k*64+i]*W1[i*64+j];
    Hb[o]=fmaxf(s,0.f);}
  __syncthreads();
  for(int o=t;o<1024;o+=256){int k=o>>6,j=o&63; float s=B2[j];
    #pragma unroll 4
    for(int i=0;i<64;i++) s+=Hb[k*64+i]*W2[i*64+j];
    Ha[o]=fmaxf(s,0.f);}
  __syncthreads();
  if(t<16){float mx=-1e30f; for(int j=0;j<64;j++) mx=fmaxf(mx,Ha[t*64+j]); wk[t]=mx;}
  __syncthreads();
  if(t==0){
    float mx=-1e30f; for(int k=0;k<16;k++) mx=fmaxf(mx,wk[k]);
    float s=0.f; for(int k=0;k<16;k++){wk[k]=expf(wk[k]-mx);s+=wk[k];}
    float inv=1.f/s; for(int k=0;k<16;k++) wk[k]*=inv;
  }
  __syncthreads();
  if(t<64){float s=0.f; for(int k=0;k<16;k++) s+=wk[k]*IN[k*68+t]; g_pcf[n*CC+t]=s;}
}

#define MLP3_SMEM (14443*4)
__global__ __launch_bounds__(256) void mlp3_kernel(
    const float* __restrict__ w0,const float* __restrict__ b0,
    const float* __restrict__ w1,const float* __restrict__ b1,
    const float* __restrict__ w2,const float* __restrict__ b2){
  extern __shared__ float sm[];
  float* W0=sm; float* W1=W0+4288; float* W2=W1+4096;
  float* B0=W2+4096; float* B1=B0+64; float* B2=B1+64;
  float* IN=B2+64; float* Ha=IN+603; float* Hb=Ha+576; float* wk=Hb+576;
  int m=blockIdx.x,t=threadIdx.x,y=m>>5,x=m&31;
  for(int i=t;i<4288;i+=256) W0[i]=w0[i];
  for(int i=t;i<4096;i+=256){W1[i]=w1[i];W2[i]=w2[i];}
  if(t<64){B0[t]=b0[t];B1[t]=b1[t];B2[t]=b2[t];}
  for(int i=t;i<9*67;i+=256){
    int k=i/67,f=i%67,dy=k/3-1,dx=k%3-1,yy=y+dy,xx=x+dx;
    float val=0.f;
    if(yy>=0&&yy<32&&xx>=0&&xx<32){int mm=yy*32+xx; val=(f<3)?g_rfi[mm*3+f]:g_rf[mm*CC+f-3];}
    IN[k*67+f]=val;
  }
  __syncthreads();
  for(int o=t;o<576;o+=256){int k=o>>6,j=o&63; float s=B0[j];
    #pragma unroll 4
    for(int i=0;i<67;i++) s+=IN[k*67+i]*W0[i*64+j];
    Ha[o]=fmaxf(s,0.f);}
  __syncthreads();
  for(int o=t;o<576;o+=256){int k=o>>6,j=o&63; float s=B1[j];
    #pragma unroll 4
    for(int i=0;i<64;i++) s+=Ha[k*64+i]*W1[i*64+j];
    Hb[o]=fmaxf(s,0.f);}
  __syncthreads();
  for(int o=t;o<576;o+=256){int k=o>>6,j=o&63; float s=B2[j];
    #pragma unroll 4
    for(int i=0;i<64;i++) s+=Hb[k*64+i]*W2[i*64+j];
    Ha[o]=fmaxf(s,0.f);}
  __syncthreads();
  if(t<9){float mx=-1e30f; for(int j=0;j<64;j++) mx=fmaxf(mx,Ha[t*64+j]); wk[t]=mx;}
  __syncthreads();
  if(t==0){
    float mx=-1e30f; for(int k=0;k<9;k++) mx=fmaxf(mx,wk[k]);
    float s=0.f; for(int k=0;k<9;k++){wk[k]=expf(wk[k]-mx);s+=wk[k];}
    float inv=1.f/s; for(int k=0;k<9;k++) wk[k]*=inv;
  }
  __syncthreads();
  if(t<64){float s=0.f; for(int k=0;k<9;k++) s+=wk[k]*IN[k*67+3+t]; g_imgf[m*CC+t]=s;}
}

__global__ void pack_kernel(){
  int m=blockIdx.x, n=threadIdx.x;
  float s1=g_sim1[m*NN+n], s2=g_sim2[m*NN+n];
  float4 q; q.x=s1*g_invc1[n]; q.y=s1*g_invr1[m]; q.z=s2*g_invc2[n]; q.w=s2*g_invr2[m];
  g_simQ[n*MM+m]=q;
}

__global__ void basem_kernel(const float* __restrict__ w1_0,const float* __restrict__ b1_0){
  int m=blockIdx.x,t=threadIdx.x;
  __shared__ float in[67];
  if(t<3) in[t]=g_rfi[m*3+t]; else if(t<67) in[t]=g_rf[m*CC+t-3];
  __syncthreads();
  float acc=b1_0[t];
  #pragma unroll
  for(int i=0;i<3;i++) acc+=in[i]*w1_0[(3+i)*128+t];
  #pragma unroll 4
  for(int i=0;i<64;i++) acc+=in[3+i]*w1_0[(70+i)*128+t];
  g_basem[m*128+t]=acc;
}
__global__ void basen_kernel(const float* __restrict__ wp,const float* __restrict__ w1_0){
  int n=blockIdx.x,t=threadIdx.x;
  __shared__ float in[67];
  if(t<3) in[t]=g_xyz[n*3+t]; else if(t<67) in[t]=wp[n*CC+t-3];
  __syncthreads();
  float acc=0.f;
  #pragma unroll
  for(int i=0;i<3;i++) acc+=in[i]*w1_0[i*128+t];
  #pragma unroll 4
  for(int i=0;i<64;i++) acc+=in[3+i]*w1_0[(6+i)*128+t];
  g_basen[n*128+t]=acc;
}

// ---------------- one-pass big kernel: 128 thr, 8x8 register tiles ----------------
#define PACK2(d,x) asm("mov.b64 %0,{%1,%1};":"=l"(d):"r"(__float_as_uint(x)))
#define FMA2(d,a,b) asm("fma.rn.f32x2 %0,%1,%2,%0;":"+l"(d):"l"(a),"l"(b))
#define UNPK(a,d0,d1) { unsigned int _lo,_hi; asm("mov.b64 {%0,%1},%2;":"=r"(_lo),"=r"(_hi):"l"(a)); d0=__uint_as_float(_lo); d1=__uint_as_float(_hi); }

#define B_WA 0
#define B_WB 8192
#define B_BA 12288
#define B_BB 12352
#define B_WS 12416
#define B_BN 12928
#define B_H1 13056
#define B_H2 29568
#define B_RM 38272
#define B_EE 38400
#define B_SC 38528
#define B_AS 38656
#define B_CO 38720
#define B_ZS 38724
#define B_MS 38725
#define B_AL 38726
#define BIG_SMEM (38728*4)

__global__ __launch_bounds__(128,1) void big_kernel(
    const float* __restrict__ w1_0,const float* __restrict__ w1_1,const float* __restrict__ b1_1,
    const float* __restrict__ w1_2,const float* __restrict__ b1_2){
  extern __shared__ float sm[];
  float* WA=sm+B_WA; float* WB=sm+B_WB; float* BA=sm+B_BA; float* BB=sm+B_BB;
  float* WS=sm+B_WS; float* BN=sm+B_BN; float* H1=sm+B_H1; float* H2=sm+B_H2;
  float* RM=sm+B_RM; float* EE=sm+B_EE; float* SC=sm+B_SC; float* AS=sm+B_AS;
  float* CO=sm+B_CO; float* ZS=sm+B_ZS; float* MS=sm+B_MS; float* AL=sm+B_AL;
  int t=threadIdx.x, n=blockIdx.x;
  for(int i=t;i<8192;i+=128) WA[i]=w1_1[i];
  for(int i=t;i<4096;i+=128) WB[i]=w1_2[i];
  if(t<64){BA[t]=b1_1[t];BB[t]=b1_2[t];}
  for(int i=t;i<512;i+=128) WS[i]=w1_0[134*128+i];
  BN[t]=g_basen[n*128+t];
  if(t<64) AS[t]=0.f;
  if(t<4) CO[t]=0.f;
  if(t==0){ZS[0]=0.f; MS[0]=-1e30f;}
  __syncthreads();
  int rg=t>>3, cg=t&7;
  int r0=rg*8, j0=cg*8;
  float* F=H1;               // phase-C output aliases H1 (pitch 68)
  for(int tile=0;tile<8;tile++){
    int m0=tile*128;
    #pragma unroll 4
    for(int r=0;r<128;r++) H1[r*129+t]=g_basem[(m0+r)*128+t];
    __syncthreads();
    { // phase A
      float4 s4=g_simQ[n*MM+m0+t];
      #pragma unroll 8
      for(int c=0;c<128;c++){
        float h=H1[t*129+c]+BN[c]+s4.x*WS[c]+s4.y*WS[128+c]+s4.z*WS[256+c]+s4.w*WS[384+c];
        H1[t*129+c]=fmaxf(h,0.f);
      }
    }
    __syncthreads();
    { // phase B: H2 = relu(H1 @ WA + BA)
      unsigned long long acc[8][4];
      #pragma unroll
      for(int i=0;i<8;i++){
        acc[i][0]=*(const unsigned long long*)&BA[j0];
        acc[i][1]=*(const unsigned long long*)&BA[j0+2];
        acc[i][2]=*(const unsigned long long*)&BA[j0+4];
        acc[i][3]=*(const unsigned long long*)&BA[j0+6];
      }
      #pragma unroll 2
      for(int k=0;k<128;k++){
        ulonglong2 wv0=*(const ulonglong2*)&WA[k*64+j0];
        ulonglong2 wv1=*(const ulonglong2*)&WA[k*64+j0+4];
        #pragma unroll
        for(int i=0;i<8;i++){
          unsigned long long p; PACK2(p,H1[(r0+i)*129+k]);
          FMA2(acc[i][0],p,wv0.x); FMA2(acc[i][1],p,wv0.y);
          FMA2(acc[i][2],p,wv1.x); FMA2(acc[i][3],p,wv1.y);
        }
      }
      #pragma unroll
      for(int i=0;i<8;i++)
        #pragma unroll
        for(int q=0;q<4;q++){
          float x0,x1; UNPK(acc[i][q],x0,x1);
          H2[(r0+i)*68+j0+2*q]=fmaxf(x0,0.f);
          H2[(r0+i)*68+j0+2*q+1]=fmaxf(x1,0.f);
        }
    }
    __syncthreads();
    { // phase C: F = relu(H2 @ WB + BB); F aliases H1
      unsigned long long acc[8][4];
      #pragma unroll
      for(int i=0;i<8;i++){
        acc[i][0]=*(const unsigned long long*)&BB[j0];
        acc[i][1]=*(const unsigned long long*)&BB[j0+2];
        acc[i][2]=*(const unsigned long long*)&BB[j0+4];
        acc[i][3]=*(const unsigned long long*)&BB[j0+6];
      }
      #pragma unroll 2
      for(int k=0;k<64;k++){
        ulonglong2 wv0=*(const ulonglong2*)&WB[k*64+j0];
        ulonglong2 wv1=*(const ulonglong2*)&WB[k*64+j0+4];
        #pragma unroll
        for(int i=0;i<8;i++){
          unsigned long long p; PACK2(p,H2[(r0+i)*68+k]);
          FMA2(acc[i][0],p,wv0.x); FMA2(acc[i][1],p,wv0.y);
          FMA2(acc[i][2],p,wv1.x); FMA2(acc[i][3],p,wv1.y);
        }
      }
      __syncthreads();
      #pragma unroll
      for(int i=0;i<8;i++)
        #pragma unroll
        for(int q=0;q<4;q++){
          float x0,x1; UNPK(acc[i][q],x0,x1);
          F[(r0+i)*68+j0+2*q]=fmaxf(x0,0.f);
          F[(r0+i)*68+j0+2*q+1]=fmaxf(x1,0.f);
        }
    }
    __syncthreads();
    // phase D: online softmax over this 128-m tile
    {
      float mx=-1e30f;
      #pragma unroll 8
      for(int c=0;c<64;c++) mx=fmaxf(mx,F[t*68+c]);
      RM[t]=mx;
    }
    __syncthreads();
    if(t<32){
      float v=fmaxf(fmaxf(RM[t],RM[t+32]),fmaxf(RM[t+64],RM[t+96]));
      for(int o=16;o;o>>=1) v=fmaxf(v,__shfl_down_sync(~0u,v,o));
      if(t==0){ float oldM=MS[0], nM=fmaxf(oldM,v); AL[0]=expf(oldM-nM); MS[0]=nM; }
    }
    __syncthreads();
    EE[t]=expf(RM[t]-MS[0]);
    __syncthreads();
    {
      int c=t&63, half=t>>6;
      float s=0.f;
      #pragma unroll 4
      for(int r=half*64;r<half*64+64;r++) s+=EE[r]*F[r*68+c];
      SC[t]=s;
    }
    __syncthreads();
    float alpha=AL[0];
    if(t<64) AS[t]=AS[t]*alpha+SC[t]+SC[64+t];
    else if(t<96){
      int l=t&31;
      float a0=0.f,a1=0.f;
      for(int r=l;r<128;r+=32){ float e=EE[r]; a0+=e*g_rfi[(m0+r)*3+0]; a1+=e*g_rfi[(m0+r)*3+1]; }
      for(int o=16;o;o>>=1){ a0+=__shfl_down_sync(~0u,a0,o); a1+=__shfl_down_sync(~0u,a1,o); }
      if(l==0){ CO[0]=CO[0]*alpha+a0; CO[1]=CO[1]*alpha+a1; }
    } else {
      int l=t&31;
      float a2=0.f,z=0.f;
      for(int r=l;r<128;r+=32){ float e=EE[r]; a2+=e*g_rfi[(m0+r)*3+2]; z+=e; }
      for(int o=16;o;o>>=1){ a2+=__shfl_down_sync(~0u,a2,o); z+=__shfl_down_sync(~0u,z,o); }
      if(l==0){ CO[2]=CO[2]*alpha+a2; ZS[0]=ZS[0]*alpha+z; }
    }
    __syncthreads();
  }
  if(t<64) g_att[n*CC+t]=AS[t]/ZS[0];
  else if(t<67) g_corres[n*3+(t-64)]=CO[t-64]/ZS[0];
}

__global__ void head_kernel(const float* __restrict__ wm0,const float* __restrict__ bm0,
    const float* __restrict__ wm1,const float* __restrict__ bm1,
    const float* __restrict__ wm2,const float* __restrict__ bm2,float* __restrict__ outw){
  int n=blockIdx.x,t=threadIdx.x;
  __shared__ float a[64],h1[64],h2[128];
  if(t<64) a[t]=g_att[n*CC+t];
  __syncthreads();
  if(t<64){
    float s=bm0[t];
    #pragma unroll 4
    for(int k=0;k<64;k++) s+=a[k]*wm0[k*64+t];
    h1[t]=fmaxf(s,0.f);
  }
  __syncthreads();
  {
    float s=bm1[t];
    #pragma unroll 4
    for(int k=0;k<64;k++) s+=h1[k]*wm1[k*128+t];
    h2[t]=fmaxf(s,0.f);
  }
  __syncthreads();
  if(t==0){
    float l0=bm2[0],l1=bm2[1];
    for(int k=0;k<128;k++){l0+=h2[k]*wm2[k*2];l1+=h2[k]*wm2[k*2+1];}
    float mx=fmaxf(l0,l1),e0=expf(l0-mx),e1=expf(l1-mx),inv=1.f/(e0+e1);
    outw[n*2]=e0*inv; outw[n*2+1]=e1*inv;
    g_win[n]=(l1>l0)?1.f:0.f;
  }
}

__device__ float brs(float v,float* red){
  int t=threadIdx.x;
  red[t]=v; __syncthreads();
  for(int s=128;s>0;s>>=1){ if(t<s) red[t]+=red[t+s]; __syncthreads(); }
  float r=red[0]; __syncthreads();
  return r;
}

__global__ void pnp_kernel(float* __restrict__ out){
  __shared__ float red[256];
  int t=threadIdx.x;
  float w=g_win[t];
  float sx=g_xyz[t*3],sy=g_xyz[t*3+1],sz=g_xyz[t*3+2];
  float u=g_corres[t*3],v=g_corres[t*3+1];
  float dx=u*sz,dy=v*sz,dz=sz;
  float sw=brs(w,red);
  float wn=w/(sw+1e-8f);
  float scx=brs(wn*sx,red),scy=brs(wn*sy,red),scz=brs(wn*sz,red);
  float dcx=brs(wn*dx,red),dcy=brs(wn*dy,red),dcz=brs(wn*dz,red);
  float ax=sx-scx,ay=sy-scy,az=sz-scz;
  float bx=dx-dcx,by=dy-dcy,bz=dz-dcz;
  float hm[9];
  hm[0]=brs(wn*ax*bx,red);hm[1]=brs(wn*ax*by,red);hm[2]=brs(wn*ax*bz,red);
  hm[3]=brs(wn*ay*bx,red);hm[4]=brs(wn*ay*by,red);hm[5]=brs(wn*ay*bz,red);
  hm[6]=brs(wn*az*bx,red);hm[7]=brs(wn*az*by,red);hm[8]=brs(wn*az*bz,red);
  if(t==0){
    double h[3][3]={{hm[0],hm[1],hm[2]},{hm[3],hm[4],hm[5]},{hm[6],hm[7],hm[8]}};
    double A[3][3],V[3][3]={{1,0,0},{0,1,0},{0,0,1}};
    for(int i=0;i<3;i++)for(int j=0;j<3;j++){double s=0;for(int k=0;k<3;k++)s+=h[k][i]*h[k][j];A[i][j]=s;}
    const int P[3]={0,0,1},Q[3]={1,2,2};
    for(int sweep=0;sweep<20;sweep++)
      for(int r=0;r<3;r++){
        int p=P[r],qq=Q[r];
        double apq=A[p][qq];
        if(fabs(apq)<1e-300) continue;
        double tau=(A[qq][qq]-A[p][p])/(2.0*apq);
        double tt=((tau>=0)?1.0:-1.0)/(fabs(tau)+sqrt(1.0+tau*tau));
        double c=1.0/sqrt(1.0+tt*tt),s=tt*c;
        for(int k=0;k<3;k++){double a1=A[k][p],a2=A[k][qq];A[k][p]=c*a1-s*a2;A[k][qq]=s*a1+c*a2;}
        for(int k=0;k<3;k++){double a1=A[p][k],a2=A[qq][k];A[p][k]=c*a1-s*a2;A[qq][k]=s*a1+c*a2;}
        for(int k=0;k<3;k++){double v1=V[k][p],v2=V[k][qq];V[k][p]=c*v1-s*v2;V[k][qq]=s*v1+c*v2;}
      }
    double lam[3]={A[0][0],A[1][1],A[2][2]};
    int o[3]={0,1,2};
    if(lam[o[0]]<lam[o[1]]){int x=o[0];o[0]=o[1];o[1]=x;}
    if(lam[o[1]]<lam[o[2]]){int x=o[1];o[1]=o[2];o[2]=x;}
    if(lam[o[0]]<lam[o[1]]){int x=o[0];o[0]=o[1];o[1]=x;}
    double vv[3][3],uu[3][3],sg[3];
    for(int i=0;i<3;i++){
      sg[i]=sqrt(fmax(lam[o[i]],0.0));
      for(int k=0;k<3;k++) vv[i][k]=V[k][o[i]];
    }
    for(int i=0;i<2;i++){
      for(int j=0;j<3;j++){double s=0;for(int k=0;k<3;k++)s+=h[j][k]*vv[i][k];uu[i][j]=s/fmax(sg[i],1e-300);}
    }
    if(sg[2]>1e-9*sg[0]){
      for(int j=0;j<3;j++){double s=0;for(int k=0;k<3;k++)s+=h[j][k]*vv[2][k];uu[2][j]=s/sg[2];}
    } else {
      uu[2][0]=uu[0][1]*uu[1][2]-uu[0][2]*uu[1][1];
      uu[2][1]=uu[0][2]*uu[1][0]-uu[0][0]*uu[1][2];
      uu[2][2]=uu[0][0]*uu[1][1]-uu[0][1]*uu[1][0];
    }
    double detV=vv[0][0]*(vv[1][1]*vv[2][2]-vv[1][2]*vv[2][1])
               -vv[0][1]*(vv[1][0]*vv[2][2]-vv[1][2]*vv[2][0])
               +vv[0][2]*(vv[1][0]*vv[2][1]-vv[1][1]*vv[2][0]);
    double detU=uu[0][0]*(uu[1][1]*uu[2][2]-uu[1][2]*uu[2][1])
               -uu[0][1]*(uu[1][0]*uu[2][2]-uu[1][2]*uu[2][0])
               +uu[0][2]*(uu[1][0]*uu[2][1]-uu[1][1]*uu[2][0]);
    double d=detV*detU;
    double R[3][3];
    for(int i=0;i<3;i++)for(int j=0;j<3;j++)
      R[i][j]=vv[0][i]*uu[0][j]+vv[1][i]*uu[1][j]+d*vv[2][i]*uu[2][j];
    double sc[3]={scx,scy,scz},dc[3]={dcx,dcy,dcz};
    for(int i=0;i<3;i++){
      for(int j=0;j<3;j++) out[i*3+j]=(float)R[i][j];
      double s=0; for(int j=0;j<3;j++) s+=R[i][j]*sc[j];
      out[9+i]=(float)(dc[i]-s);
    }
  }
}

extern "C" void kernel_launch(void* const* d_in, const int* in_sizes, int n_in,
                              void* d_out, int out_size){
  const float* wx  =(const float*)d_in[0];
  const float* wp  =(const float*)d_in[1];
  const float* RF3 =(const float*)d_in[2];
  const float* RF3i=(const float*)d_in[3];
  const float* lz  =(const float*)d_in[4];
  const float* w2_0=(const float*)d_in[5];  const float* b2_0=(const float*)d_in[6];
  const float* w2_1=(const float*)d_in[7];  const float* b2_1=(const float*)d_in[8];
  const float* w2_2=(const float*)d_in[9];  const float* b2_2=(const float*)d_in[10];
  const float* w3_0=(const float*)d_in[11]; const float* b3_0=(const float*)d_in[12];
  const float* w3_1=(const float*)d_in[13]; const float* b3_1=(const float*)d_in[14];
  const float* w3_2=(const float*)d_in[15]; const float* b3_2=(const float*)d_in[16];
  const float* w1_0=(const float*)d_in[17]; const float* b1_0=(const float*)d_in[18];
  const float* w1_1=(const float*)d_in[19]; const float* b1_1=(const float*)d_in[20];
  const float* w1_2=(const float*)d_in[21]; const float* b1_2=(const float*)d_in[22];
  const float* wm_0=(const float*)d_in[23]; const float* bm_0=(const float*)d_in[24];
  const float* wm_1=(const float*)d_in[25]; const float* bm_1=(const float*)d_in[26];
  const float* wm_2=(const float*)d_in[27]; const float* bm_2=(const float*)d_in[28];
  float* out=(float*)d_out;

  cudaFuncSetAttribute(mlp2_kernel, cudaFuncAttributeMaxDynamicSharedMemorySize, MLP2_SMEM);
  cudaFuncSetAttribute(mlp3_kernel, cudaFuncAttributeMaxDynamicSharedMemorySize, MLP3_SMEM);
  cudaFuncSetAttribute(big_kernel,  cudaFuncAttributeMaxDynamicSharedMemorySize, BIG_SMEM);

  prep_kernel<<<MM,64>>>(wx,lz,RF3,RF3i);
  l2norm_kernel<<<NN,64>>>(wp,0);
  l2norm_kernel<<<MM,64>>>(nullptr,1);
  corr_kernel<<<dim3(MM/64,NN/64),256>>>(0);
  colmax_kernel<<<NN,128>>>(0);
  rowmax_kernel<<<MM/8,256>>>(0);
  knn_kernel<<<NN,256>>>();
  mlp2_kernel<<<NN,256,MLP2_SMEM>>>(wp,w2_0,b2_0,w2_1,b2_1,w2_2,b2_2);
  mlp3_kernel<<<MM,256,MLP3_SMEM>>>(w3_0,b3_0,w3_1,b3_1,w3_2,b3_2);
  l2norm_kernel<<<NN,64>>>(nullptr,2);
  l2norm_kernel<<<MM,64>>>(nullptr,3);
  corr_kernel<<<dim3(MM/64,NN/64),256>>>(1);
  colmax_kernel<<<NN,128>>>(1);
  rowmax_kernel<<<MM/8,256>>>(1);
  pack_kernel<<<MM,NN>>>();
  basem_kernel<<<MM,128>>>(w1_0,b1_0);
  basen_kernel<<<NN,128>>>(wp,w1_0);
  big_kernel<<<NN,128,BIG_SMEM>>>(w1_0,w1_1,b1_1,w1_2,b1_2);
  head_kernel<<<NN,128>>>(wm_0,bm_0,wm_1,bm_1,wm_2,bm_2,out+12);
  pnp_kernel<<<1,NN>>>(out);
}

// round 13
// speedup vs baseline: 1.2491x; 1.1602x over previous
#include <cuda_runtime.h>
#include <math.h>

#define NN 256
#define MM 1024
#define CC 64
#define KK 16

__device__ float g_xyz[NN*3];
__device__ float g_rf[MM*CC];
__device__ float g_rfi[MM*3];
__device__ float g_wpn[NN*CC];
__device__ float g_rfn[MM*CC];
__device__ float g_sim1[MM*NN];
__device__ float g_sim2[MM*NN];
__device__ float g_invc1[NN], g_invr1[MM], g_invc2[NN], g_invr2[MM];
__device__ int   g_knn[NN*KK];
__device__ float g_pcf[NN*CC];
__device__ float g_imgf[MM*CC];
__device__ float g_pcn[NN*CC];
__device__ float g_imgn[MM*CC];
__device__ float4 g_simQ[NN*MM];
__device__ float g_basem[MM*128];
__device__ float g_basen[NN*128];
__device__ float g_att[NN*CC];
__device__ float g_corres[NN*3];
__device__ float g_win[NN];

__global__ void prep_kernel(const float* __restrict__ wx, const float* __restrict__ lz,
                            const float* __restrict__ RF3, const float* __restrict__ RF3i){
  int m=blockIdx.x, t=threadIdx.x;
  g_rf[m*CC+t]=RF3[t*MM+m];
  if(t<3) g_rfi[m*3+t]=RF3i[t*MM+m];
  if(m<NN&&t<3) g_xyz[m*3+t]=wx[m*3+t]*lz[m];
}

__global__ void l2norm_kernel(const float* __restrict__ ext,int sel){
  const float* src; float* dst;
  if(sel==0){src=ext;dst=g_wpn;} else if(sel==1){src=g_rf;dst=g_rfn;}
  else if(sel==2){src=g_pcf;dst=g_pcn;} else {src=g_imgf;dst=g_imgn;}
  int r=blockIdx.x,t=threadIdx.x;
  float v=src[r*CC+t], s=v*v;
  for(int o=16;o;o>>=1) s+=__shfl_down_sync(~0u,s,o);
  __shared__ float sh[2];
  if((t&31)==0) sh[t>>5]=s;
  __syncthreads();
  float n=fmaxf(sqrtf(sh[0]+sh[1]),1e-12f);
  dst[r*CC+t]=v/n;
}

__global__ __launch_bounds__(256) void corr_kernel(int sel){
  const float *A,*B; float* S;
  if(sel==0){A=g_rfn;B=g_wpn;S=g_sim1;} else {A=g_imgn;B=g_pcn;S=g_sim2;}
  __shared__ float As[64][65], Bs[64][65];
  int t=threadIdx.x, tx=t&15, ty=t>>4;
  int m0=blockIdx.x*64, n0=blockIdx.y*64;
  #pragma unroll
  for(int i=0;i<16;i++){int idx=t+i*256,r=idx>>6,c=idx&63;
    As[r][c]=A[(m0+r)*CC+c]; Bs[r][c]=B[(n0+r)*CC+c];}
  __syncthreads();
  float acc[4][4];
  #pragma unroll
  for(int i=0;i<4;i++)
    #pragma unroll
    for(int j=0;j<4;j++) acc[i][j]=0.f;
  #pragma unroll 8
  for(int k=0;k<64;k++){
    float a[4],b[4];
    #pragma unroll
    for(int i=0;i<4;i++){a[i]=As[ty*4+i][k]; b[i]=Bs[tx*4+i][k];}
    #pragma unroll
    for(int i=0;i<4;i++)
      #pragma unroll
      for(int j=0;j<4;j++) acc[i][j]+=a[i]*b[j];
  }
  #pragma unroll
  for(int i=0;i<4;i++)
    #pragma unroll
    for(int j=0;j<4;j++) S[(m0+ty*4+i)*NN+n0+tx*4+j]=acc[i][j];
}

__global__ void colmax_kernel(int sel){
  const float* S=sel?g_sim2:g_sim1; float* ic=sel?g_invc2:g_invc1;
  int n=blockIdx.x, t=threadIdx.x;
  float mx=-1e30f;
  for(int m=t;m<MM;m+=128) mx=fmaxf(mx,S[m*NN+n]);
  for(int o=16;o;o>>=1) mx=fmaxf(mx,__shfl_down_sync(~0u,mx,o));
  __shared__ float sh[4];
  if((t&31)==0) sh[t>>5]=mx;
  __syncthreads();
  if(t==0){
    mx=fmaxf(fmaxf(sh[0],sh[1]),fmaxf(sh[2],sh[3]));
    ic[n]=1.f/(mx+1e-6f);
  }
}
__global__ void rowmax_kernel(int sel){
  const float* S=sel?g_sim2:g_sim1; float* ir=sel?g_invr2:g_invr1;
  int w=threadIdx.x>>5,l=threadIdx.x&31,m=blockIdx.x*8+w;
  float mx=-1e30f;
  for(int n=l;n<NN;n+=32) mx=fmaxf(mx,S[m*NN+n]);
  for(int o=16;o;o>>=1) mx=fmaxf(mx,__shfl_down_sync(~0u,mx,o));
  if(l==0) ir[m]=1.f/(mx+1e-10f);
}

__global__ void knn_kernel(){
  int n=blockIdx.x,t=threadIdx.x;
  __shared__ float sx[NN*3], d2[NN], wm[8];
  __shared__ int wi[8];
  for(int i=t;i<NN*3;i+=256) sx[i]=g_xyz[i];
  __syncthreads();
  float cx=sx[n*3],cy=sx[n*3+1],cz=sx[n*3+2];
  float dx=sx[t*3]-cx,dy=sx[t*3+1]-cy,dz=sx[t*3+2]-cz;
  d2[t]=dx*dx+dy*dy+dz*dz;
  __syncthreads();
  for(int it=0;it<KK;it++){
    float v=d2[t]; int id=t;
    for(int o=16;o;o>>=1){
      float ov=__shfl_down_sync(~0u,v,o); int oi=__shfl_down_sync(~0u,id,o);
      if(ov<v||(ov==v&&oi<id)){v=ov;id=oi;}
    }
    if((t&31)==0){wm[t>>5]=v;wi[t>>5]=id;}
    __syncthreads();
    if(t==0){
      float bv=wm[0];int bi=wi[0];
      for(int w=1;w<8;w++) if(wm[w]<bv||(wm[w]==bv&&wi[w]<bi)){bv=wm[w];bi=wi[w];}
      g_knn[n*KK+it]=bi; d2[bi]=1e38f;
    }
    __syncthreads();
  }
}

#define MLP2_SMEM (15888*4)
__global__ __launch_bounds__(256) void mlp2_kernel(const float* __restrict__ wp,
    const float* __restrict__ w0,const float* __restrict__ b0,
    const float* __restrict__ w1,const float* __restrict__ b1,
    const float* __restrict__ w2,const float* __restrict__ b2){
  extern __shared__ float sm[];
  float* W0=sm; float* W1=W0+4352; float* W2=W1+4096;
  float* B0=W2+4096; float* B1=B0+64; float* B2=B1+64;
  float* IN=B2+64; float* Ha=IN+1088; float* Hb=Ha+1024; float* wk=Hb+1024;
  int n=blockIdx.x,t=threadIdx.x;
  for(int i=t;i<4352;i+=256) W0[i]=w0[i];
  for(int i=t;i<4096;i+=256){W1[i]=w1[i];W2[i]=w2[i];}
  if(t<64){B0[t]=b0[t];B1[t]=b1[t];B2[t]=b2[t];}
  for(int i=t;i<16*68;i+=256){
    int k=i/68,f=i%68,nb=g_knn[n*KK+k]; float val;
    if(f<64) val=wp[nb*CC+f];
    else if(f<67) val=g_xyz[nb*3+(f-64)]-g_xyz[n*3+(f-64)];
    else{
      float dx=g_xyz[nb*3]-g_xyz[n*3],dy=g_xyz[nb*3+1]-g_xyz[n*3+1],dz=g_xyz[nb*3+2]-g_xyz[n*3+2];
      val=sqrtf(dx*dx+dy*dy+dz*dz);
    }
    IN[k*68+f]=val;
  }
  __syncthreads();
  for(int o=t;o<1024;o+=256){int k=o>>6,j=o&63; float s=B0[j];
    #pragma unroll 4
    for(int i=0;i<68;i++) s+=IN[k*68+i]*W0[i*64+j];
    Ha[o]=fmaxf(s,0.f);}
  __syncthreads();
  for(int o=t;o<1024;o+=256){int k=o>>6,j=o&63; float s=B1[j];
    #pragma unroll 4
    for(int i=0;i<64;i++) s+=Ha[k*64+i]*W1[i*64+j];
    Hb[o]=fmaxf(s,0.f);}
  __syncthreads();
  for(int o=t;o<1024;o+=256){int k=o>>6,j=o&63; float s=B2[j];
    #pragma unroll 4
    for(int i=0;i<64;i++) s+=Hb[k*64+i]*W2[i*64+j];
    Ha[o]=fmaxf(s,0.f);}
  __syncthreads();
  if(t<16){float mx=-1e30f; for(int j=0;j<64;j++) mx=fmaxf(mx,Ha[t*64+j]); wk[t]=mx;}
  __syncthreads();
  if(t==0){
    float mx=-1e30f; for(int k=0;k<16;k++) mx=fmaxf(mx,wk[k]);
    float s=0.f; for(int k=0;k<16;k++){wk[k]=expf(wk[k]-mx);s+=wk[k];}
    float inv=1.f/s; for(int k=0;k<16;k++) wk[k]*=inv;
  }
  __syncthreads();
  if(t<64){float s=0.f; for(int k=0;k<16;k++) s+=wk[k]*IN[k*68+t]; g_pcf[n*CC+t]=s;}
}

#define MLP3_SMEM (14443*4)
__global__ __launch_bounds__(256) void mlp3_kernel(
    const float* __restrict__ w0,const float* __restrict__ b0,
    const float* __restrict__ w1,const float* __restrict__ b1,
    const float* __restrict__ w2,const float* __restrict__ b2){
  extern __shared__ float sm[];
  float* W0=sm; float* W1=W0+4288; float* W2=W1+4096;
  float* B0=W2+4096; float* B1=B0+64; float* B2=B1+64;
  float* IN=B2+64; float* Ha=IN+603; float* Hb=Ha+576; float* wk=Hb+576;
  int m=blockIdx.x,t=threadIdx.x,y=m>>5,x=m&31;
  for(int i=t;i<4288;i+=256) W0[i]=w0[i];
  for(int i=t;i<4096;i+=256){W1[i]=w1[i];W2[i]=w2[i];}
  if(t<64){B0[t]=b0[t];B1[t]=b1[t];B2[t]=b2[t];}
  for(int i=t;i<9*67;i+=256){
    int k=i/67,f=i%67,dy=k/3-1,dx=k%3-1,yy=y+dy,xx=x+dx;
    float val=0.f;
    if(yy>=0&&yy<32&&xx>=0&&xx<32){int mm=yy*32+xx; val=(f<3)?g_rfi[mm*3+f]:g_rf[mm*CC+f-3];}
    IN[k*67+f]=val;
  }
  __syncthreads();
  for(int o=t;o<576;o+=256){int k=o>>6,j=o&63; float s=B0[j];
    #pragma unroll 4
    for(int i=0;i<67;i++) s+=IN[k*67+i]*W0[i*64+j];
    Ha[o]=fmaxf(s,0.f);}
  __syncthreads();
  for(int o=t;o<576;o+=256){int k=o>>6,j=o&63; float s=B1[j];
    #pragma unroll 4
    for(int i=0;i<64;i++) s+=Ha[k*64+i]*W1[i*64+j];
    Hb[o]=fmaxf(s,0.f);}
  __syncthreads();
  for(int o=t;o<576;o+=256){int k=o>>6,j=o&63; float s=B2[j];
    #pragma unroll 4
    for(int i=0;i<64;i++) s+=Hb[k*64+i]*W2[i*64+j];
    Ha[o]=fmaxf(s,0.f);}
  __syncthreads();
  if(t<9){float mx=-1e30f; for(int j=0;j<64;j++) mx=fmaxf(mx,Ha[t*64+j]); wk[t]=mx;}
  __syncthreads();
  if(t==0){
    float mx=-1e30f; for(int k=0;k<9;k++) mx=fmaxf(mx,wk[k]);
    float s=0.f; for(int k=0;k<9;k++){wk[k]=expf(wk[k]-mx);s+=wk[k];}
    float inv=1.f/s; for(int k=0;k<9;k++) wk[k]*=inv;
  }
  __syncthreads();
  if(t<64){float s=0.f; for(int k=0;k<9;k++) s+=wk[k]*IN[k*67+3+t]; g_imgf[m*CC+t]=s;}
}

__global__ void pack_kernel(){
  int m=blockIdx.x, n=threadIdx.x;
  float s1=g_sim1[m*NN+n], s2=g_sim2[m*NN+n];
  float4 q; q.x=s1*g_invc1[n]; q.y=s1*g_invr1[m]; q.z=s2*g_invc2[n]; q.w=s2*g_invr2[m];
  g_simQ[n*MM+m]=q;
}

__global__ void basem_kernel(const float* __restrict__ w1_0,const float* __restrict__ b1_0){
  int m=blockIdx.x,t=threadIdx.x;
  __shared__ float in[67];
  if(t<3) in[t]=g_rfi[m*3+t]; else if(t<67) in[t]=g_rf[m*CC+t-3];
  __syncthreads();
  float acc=b1_0[t];
  #pragma unroll
  for(int i=0;i<3;i++) acc+=in[i]*w1_0[(3+i)*128+t];
  #pragma unroll 4
  for(int i=0;i<64;i++) acc+=in[3+i]*w1_0[(70+i)*128+t];
  g_basem[m*128+t]=acc;
}
__global__ void basen_kernel(const float* __restrict__ wp,const float* __restrict__ w1_0){
  int n=blockIdx.x,t=threadIdx.x;
  __shared__ float in[67];
  if(t<3) in[t]=g_xyz[n*3+t]; else if(t<67) in[t]=wp[n*CC+t-3];
  __syncthreads();
  float acc=0.f;
  #pragma unroll
  for(int i=0;i<3;i++) acc+=in[i]*w1_0[i*128+t];
  #pragma unroll 4
  for(int i=0;i<64;i++) acc+=in[3+i]*w1_0[(6+i)*128+t];
  g_basen[n*128+t]=acc;
}

// ---- one-pass big kernel: 128 thr, 64-row m-tiles, 4x8 f32x2 tiles, 2 CTA/SM ----
#define PACK2(d,x) asm("mov.b64 %0,{%1,%1};":"=l"(d):"r"(__float_as_uint(x)))
#define FMA2(d,a,b) asm("fma.rn.f32x2 %0,%1,%2,%0;":"+l"(d):"l"(a),"l"(b))
#define UNPK(a,d0,d1) { unsigned int _lo,_hi; asm("mov.b64 {%0,%1},%2;":"=r"(_lo),"=r"(_hi):"l"(a)); d0=__uint_as_float(_lo); d1=__uint_as_float(_hi); }

#define B_WA 0
#define B_WB 8192
#define B_BA 12288
#define B_BB 12352
#define B_WS 12416
#define B_BN 12928
#define B_H1 13056
#define B_H2 21312
#define B_RM 25664
#define B_EE 25728
#define B_SC 25792
#define B_AS 25920
#define B_CO 25984
#define B_ZS 25988
#define B_MS 25989
#define B_AL 25990
#define BIG_SMEM (25992*4)

__global__ __launch_bounds__(128,2) void big_kernel(
    const float* __restrict__ w1_0,const float* __restrict__ w1_1,const float* __restrict__ b1_1,
    const float* __restrict__ w1_2,const float* __restrict__ b1_2){
  extern __shared__ float sm[];
  float* WA=sm+B_WA; float* WB=sm+B_WB; float* BA=sm+B_BA; float* BB=sm+B_BB;
  float* WS=sm+B_WS; float* BN=sm+B_BN; float* H1=sm+B_H1; float* H2=sm+B_H2;
  float* RM=sm+B_RM; float* EE=sm+B_EE; float* SC=sm+B_SC; float* AS=sm+B_AS;
  float* CO=sm+B_CO; float* ZS=sm+B_ZS; float* MS=sm+B_MS; float* AL=sm+B_AL;
  int t=threadIdx.x, n=blockIdx.x;
  for(int i=t;i<8192;i+=128) WA[i]=w1_1[i];
  for(int i=t;i<4096;i+=128) WB[i]=w1_2[i];
  if(t<64){BA[t]=b1_1[t];BB[t]=b1_2[t];}
  for(int i=t;i<512;i+=128) WS[i]=w1_0[134*128+i];
  BN[t]=g_basen[n*128+t];
  if(t<64) AS[t]=0.f;
  if(t<4) CO[t]=0.f;
  if(t==0){ZS[0]=0.f; MS[0]=-1e30f;}
  __syncthreads();
  int rg=t>>3, cg=t&7;          // 16 rowgroups x 8 colgroups
  int r0=rg*4, j0=cg*8;
  float* F=H1;                  // phase-C output aliases H1 (pitch 68)
  for(int tile=0;tile<16;tile++){
    int m0=tile*64;
    // load basem tile, coalesced
    #pragma unroll 4
    for(int idx=t;idx<64*128;idx+=128){int r=idx>>7,c=idx&127; H1[r*129+c]=g_basem[(m0+r)*128+c];}
    __syncthreads();
    { // phase A: H1 = relu(basem + basen + sim4@WS); row=t&63, colgroup=t>>6
      int row=t&63, ch=t>>6;
      float4 s4=g_simQ[n*MM+m0+row];
      #pragma unroll 8
      for(int i=0;i<64;i++){
        int c=ch*64+i;
        float h=H1[row*129+c]+BN[c]+s4.x*WS[c]+s4.y*WS[128+c]+s4.z*WS[256+c]+s4.w*WS[384+c];
        H1[row*129+c]=fmaxf(h,0.f);
      }
    }
    __syncthreads();
    { // phase B: H2[64x64] = relu(H1[64x128] @ WA + BA), 4x8 per thread
      unsigned long long acc[4][4];
      #pragma unroll
      for(int i=0;i<4;i++){
        acc[i][0]=*(const unsigned long long*)&BA[j0];
        acc[i][1]=*(const unsigned long long*)&BA[j0+2];
        acc[i][2]=*(const unsigned long long*)&BA[j0+4];
        acc[i][3]=*(const unsigned long long*)&BA[j0+6];
      }
      #pragma unroll 4
      for(int k=0;k<128;k++){
        ulonglong2 wv0=*(const ulonglong2*)&WA[k*64+j0];
        ulonglong2 wv1=*(const ulonglong2*)&WA[k*64+j0+4];
        #pragma unroll
        for(int i=0;i<4;i++){
          unsigned long long p; PACK2(p,H1[(r0+i)*129+k]);
          FMA2(acc[i][0],p,wv0.x); FMA2(acc[i][1],p,wv0.y);
          FMA2(acc[i][2],p,wv1.x); FMA2(acc[i][3],p,wv1.y);
        }
      }
      #pragma unroll
      for(int i=0;i<4;i++)
        #pragma unroll
        for(int q=0;q<4;q++){
          float x0,x1; UNPK(acc[i][q],x0,x1);
          H2[(r0+i)*68+j0+2*q]=fmaxf(x0,0.f);
          H2[(r0+i)*68+j0+2*q+1]=fmaxf(x1,0.f);
        }
    }
    __syncthreads();
    { // phase C: F[64x64] = relu(H2 @ WB + BB); F aliases H1 (dead)
      unsigned long long acc[4][4];
      #pragma unroll
      for(int i=0;i<4;i++){
        acc[i][0]=*(const unsigned long long*)&BB[j0];
        acc[i][1]=*(const unsigned long long*)&BB[j0+2];
        acc[i][2]=*(const unsigned long long*)&BB[j0+4];
        acc[i][3]=*(const unsigned long long*)&BB[j0+6];
      }
      #pragma unroll 4
      for(int k=0;k<64;k++){
        ulonglong2 wv0=*(const ulonglong2*)&WB[k*64+j0];
        ulonglong2 wv1=*(const ulonglong2*)&WB[k*64+j0+4];
        #pragma unroll
        for(int i=0;i<4;i++){
          unsigned long long p; PACK2(p,H2[(r0+i)*68+k]);
          FMA2(acc[i][0],p,wv0.x); FMA2(acc[i][1],p,wv0.y);
          FMA2(acc[i][2],p,wv1.x); FMA2(acc[i][3],p,wv1.y);
        }
      }
      __syncthreads();   // all H1 reads done block-wide before F(=H1) writes
      #pragma unroll
      for(int i=0;i<4;i++)
        #pragma unroll
        for(int q=0;q<4;q++){
          float x0,x1; UNPK(acc[i][q],x0,x1);
          F[(r0+i)*68+j0+2*q]=fmaxf(x0,0.f);
          F[(r0+i)*68+j0+2*q+1]=fmaxf(x1,0.f);
        }
    }
    __syncthreads();
    // phase D: online softmax over this 64-m tile
    if(t<64){
      float mx=-1e30f;
      #pragma unroll 8
      for(int c=0;c<64;c++) mx=fmaxf(mx,F[t*68+c]);
      RM[t]=mx;
    }
    __syncthreads();
    if(t<32){
      float v=fmaxf(RM[t],RM[t+32]);
      for(int o=16;o;o>>=1) v=fmaxf(v,__shfl_down_sync(~0u,v,o));
      if(t==0){ float oldM=MS[0], nM=fmaxf(oldM,v); AL[0]=expf(oldM-nM); MS[0]=nM; }
    }
    __syncthreads();
    if(t<64) EE[t]=expf(RM[t]-MS[0]);
    __syncthreads();
    { // att partials: 128 threads, c=t&63, half=t>>6 covers rows half*32..+32
      int c=t&63, half=t>>6;
      float s=0.f;
      #pragma unroll 4
      for(int r=half*32;r<half*32+32;r++) s+=EE[r]*F[r*68+c];
      SC[t]=s;
    }
    __syncthreads();
    float alpha=AL[0];
    if(t<64) AS[t]=AS[t]*alpha+SC[t]+SC[64+t];
    else if(t<96){
      int l=t&31;
      float a0=0.f,a1=0.f;
      for(int r=l;r<64;r+=32){ float e=EE[r]; a0+=e*g_rfi[(m0+r)*3+0]; a1+=e*g_rfi[(m0+r)*3+1]; }
      for(int o=16;o;o>>=1){ a0+=__shfl_down_sync(~0u,a0,o); a1+=__shfl_down_sync(~0u,a1,o); }
      if(l==0){ CO[0]=CO[0]*alpha+a0; CO[1]=CO[1]*alpha+a1; }
    } else {
      int l=t&31;
      float a2=0.f,z=0.f;
      for(int r=l;r<64;r+=32){ float e=EE[r]; a2+=e*g_rfi[(m0+r)*3+2]; z+=e; }
      for(int o=16;o;o>>=1){ a2+=__shfl_down_sync(~0u,a2,o); z+=__shfl_down_sync(~0u,z,o); }
      if(l==0){ CO[2]=CO[2]*alpha+a2; ZS[0]=ZS[0]*alpha+z; }
    }
    __syncthreads();
  }
  if(t<64) g_att[n*CC+t]=AS[t]/ZS[0];
  else if(t<67) g_corres[n*3+(t-64)]=CO[t-64]/ZS[0];
}

__global__ void head_kernel(const float* __restrict__ wm0,const float* __restrict__ bm0,
    const float* __restrict__ wm1,const float* __restrict__ bm1,
    const float* __restrict__ wm2,const float* __restrict__ bm2,float* __restrict__ outw){
  int n=blockIdx.x,t=threadIdx.x;
  __shared__ float a[64],h1[64],h2[128];
  if(t<64) a[t]=g_att[n*CC+t];
  __syncthreads();
  if(t<64){
    float s=bm0[t];
    #pragma unroll 4
    for(int k=0;k<64;k++) s+=a[k]*wm0[k*64+t];
    h1[t]=fmaxf(s,0.f);
  }
  __syncthreads();
  {
    float s=bm1[t];
    #pragma unroll 4
    for(int k=0;k<64;k++) s+=h1[k]*wm1[k*128+t];
    h2[t]=fmaxf(s,0.f);
  }
  __syncthreads();
  if(t==0){
    float l0=bm2[0],l1=bm2[1];
    for(int k=0;k<128;k++){l0+=h2[k]*wm2[k*2];l1+=h2[k]*wm2[k*2+1];}
    float mx=fmaxf(l0,l1),e0=expf(l0-mx),e1=expf(l1-mx),inv=1.f/(e0+e1);
    outw[n*2]=e0*inv; outw[n*2+1]=e1*inv;
    g_win[n]=(l1>l0)?1.f:0.f;
  }
}

__device__ float brs(float v,float* red){
  int t=threadIdx.x;
  red[t]=v; __syncthreads();
  for(int s=128;s>0;s>>=1){ if(t<s) red[t]+=red[t+s]; __syncthreads(); }
  float r=red[0]; __syncthreads();
  return r;
}

__global__ void pnp_kernel(float* __restrict__ out){
  __shared__ float red[256];
  int t=threadIdx.x;
  float w=g_win[t];
  float sx=g_xyz[t*3],sy=g_xyz[t*3+1],sz=g_xyz[t*3+2];
  float u=g_corres[t*3],v=g_corres[t*3+1];
  float dx=u*sz,dy=v*sz,dz=sz;
  float sw=brs(w,red);
  float wn=w/(sw+1e-8f);
  float scx=brs(wn*sx,red),scy=brs(wn*sy,red),scz=brs(wn*sz,red);
  float dcx=brs(wn*dx,red),dcy=brs(wn*dy,red),dcz=brs(wn*dz,red);
  float ax=sx-scx,ay=sy-scy,az=sz-scz;
  float bx=dx-dcx,by=dy-dcy,bz=dz-dcz;
  float hm[9];
  hm[0]=brs(wn*ax*bx,red);hm[1]=brs(wn*ax*by,red);hm[2]=brs(wn*ax*bz,red);
  hm[3]=brs(wn*ay*bx,red);hm[4]=brs(wn*ay*by,red);hm[5]=brs(wn*ay*bz,red);
  hm[6]=brs(wn*az*bx,red);hm[7]=brs(wn*az*by,red);hm[8]=brs(wn*az*bz,red);
  if(t==0){
    double h[3][3]={{hm[0],hm[1],hm[2]},{hm[3],hm[4],hm[5]},{hm[6],hm[7],hm[8]}};
    double A[3][3],V[3][3]={{1,0,0},{0,1,0},{0,0,1}};
    for(int i=0;i<3;i++)for(int j=0;j<3;j++){double s=0;for(int k=0;k<3;k++)s+=h[k][i]*h[k][j];A[i][j]=s;}
    const int P[3]={0,0,1},Q[3]={1,2,2};
    for(int sweep=0;sweep<20;sweep++)
      for(int r=0;r<3;r++){
        int p=P[r],qq=Q[r];
        double apq=A[p][qq];
        if(fabs(apq)<1e-300) continue;
        double tau=(A[qq][qq]-A[p][p])/(2.0*apq);
        double tt=((tau>=0)?1.0:-1.0)/(fabs(tau)+sqrt(1.0+tau*tau));
        double c=1.0/sqrt(1.0+tt*tt),s=tt*c;
        for(int k=0;k<3;k++){double a1=A[k][p],a2=A[k][qq];A[k][p]=c*a1-s*a2;A[k][qq]=s*a1+c*a2;}
        for(int k=0;k<3;k++){double a1=A[p][k],a2=A[qq][k];A[p][k]=c*a1-s*a2;A[qq][k]=s*a1+c*a2;}
        for(int k=0;k<3;k++){double v1=V[k][p],v2=V[k][qq];V[k][p]=c*v1-s*v2;V[k][qq]=s*v1+c*v2;}
      }
    double lam[3]={A[0][0],A[1][1],A[2][2]};
    int o[3]={0,1,2};
    if(lam[o[0]]<lam[o[1]]){int x=o[0];o[0]=o[1];o[1]=x;}
    if(lam[o[1]]<lam[o[2]]){int x=o[1];o[1]=o[2];o[2]=x;}
    if(lam[o[0]]<lam[o[1]]){int x=o[0];o[0]=o[1];o[1]=x;}
    double vv[3][3],uu[3][3],sg[3];
    for(int i=0;i<3;i++){
      sg[i]=sqrt(fmax(lam[o[i]],0.0));
      for(int k=0;k<3;k++) vv[i][k]=V[k][o[i]];
    }
    for(int i=0;i<2;i++){
      for(int j=0;j<3;j++){double s=0;for(int k=0;k<3;k++)s+=h[j][k]*vv[i][k];uu[i][j]=s/fmax(sg[i],1e-300);}
    }
    if(sg[2]>1e-9*sg[0]){
      for(int j=0;j<3;j++){double s=0;for(int k=0;k<3;k++)s+=h[j][k]*vv[2][k];uu[2][j]=s/sg[2];}
    } else {
      uu[2][0]=uu[0][1]*uu[1][2]-uu[0][2]*uu[1][1];
      uu[2][1]=uu[0][2]*uu[1][0]-uu[0][0]*uu[1][2];
      uu[2][2]=uu[0][0]*uu[1][1]-uu[0][1]*uu[1][0];
    }
    double detV=vv[0][0]*(vv[1][1]*vv[2][2]-vv[1][2]*vv[2][1])
               -vv[0][1]*(vv[1][0]*vv[2][2]-vv[1][2]*vv[2][0])
               +vv[0][2]*(vv[1][0]*vv[2][1]-vv[1][1]*vv[2][0]);
    double detU=uu[0][0]*(uu[1][1]*uu[2][2]-uu[1][2]*uu[2][1])
               -uu[0][1]*(uu[1][0]*uu[2][2]-uu[1][2]*uu[2][0])
               +uu[0][2]*(uu[1][0]*uu[2][1]-uu[1][1]*uu[2][0]);
    double d=detV*detU;
    double R[3][3];
    for(int i=0;i<3;i++)for(int j=0;j<3;j++)
      R[i][j]=vv[0][i]*uu[0][j]+vv[1][i]*uu[1][j]+d*vv[2][i]*uu[2][j];
    double sc[3]={scx,scy,scz},dc[3]={dcx,dcy,dcz};
    for(int i=0;i<3;i++){
      for(int j=0;j<3;j++) out[i*3+j]=(float)R[i][j];
      double s=0; for(int j=0;j<3;j++) s+=R[i][j]*sc[j];
      out[9+i]=(float)(dc[i]-s);
    }
  }
}

extern "C" void kernel_launch(void* const* d_in, const int* in_sizes, int n_in,
                              void* d_out, int out_size){
  const float* wx  =(const float*)d_in[0];
  const float* wp  =(const float*)d_in[1];
  const float* RF3 =(const float*)d_in[2];
  const float* RF3i=(const float*)d_in[3];
  const float* lz  =(const float*)d_in[4];
  const float* w2_0=(const float*)d_in[5];  const float* b2_0=(const float*)d_in[6];
  const float* w2_1=(const float*)d_in[7];  const float* b2_1=(const float*)d_in[8];
  const float* w2_2=(const float*)d_in[9];  const float* b2_2=(const float*)d_in[10];
  const float* w3_0=(const float*)d_in[11]; const float* b3_0=(const float*)d_in[12];
  const float* w3_1=(const float*)d_in[13]; const float* b3_1=(const float*)d_in[14];
  const float* w3_2=(const float*)d_in[15]; const float* b3_2=(const float*)d_in[16];
  const float* w1_0=(const float*)d_in[17]; const float* b1_0=(const float*)d_in[18];
  const float* w1_1=(const float*)d_in[19]; const float* b1_1=(const float*)d_in[20];
  const float* w1_2=(const float*)d_in[21]; const float* b1_2=(const float*)d_in[22];
  const float* wm_0=(const float*)d_in[23]; const float* bm_0=(const float*)d_in[24];
  const float* wm_1=(const float*)d_in[25]; const float* bm_1=(const float*)d_in[26];
  const float* wm_2=(const float*)d_in[27]; const float* bm_2=(const float*)d_in[28];
  float* out=(float*)d_out;

  cudaFuncSetAttribute(mlp2_kernel, cudaFuncAttributeMaxDynamicSharedMemorySize, MLP2_SMEM);
  cudaFuncSetAttribute(mlp3_kernel, cudaFuncAttributeMaxDynamicSharedMemorySize, MLP3_SMEM);
  cudaFuncSetAttribute(big_kernel,  cudaFuncAttributeMaxDynamicSharedMemorySize, BIG_SMEM);

  prep_kernel<<<MM,64>>>(wx,lz,RF3,RF3i);
  l2norm_kernel<<<NN,64>>>(wp,0);
  l2norm_kernel<<<MM,64>>>(nullptr,1);
  corr_kernel<<<dim3(MM/64,NN/64),256>>>(0);
  colmax_kernel<<<NN,128>>>(0);
  rowmax_kernel<<<MM/8,256>>>(0);
  knn_kernel<<<NN,256>>>();
  mlp2_kernel<<<NN,256,MLP2_SMEM>>>(wp,w2_0,b2_0,w2_1,b2_1,w2_2,b2_2);
  mlp3_kernel<<<MM,256,MLP3_SMEM>>>(w3_0,b3_0,w3_1,b3_1,w3_2,b3_2);
  l2norm_kernel<<<NN,64>>>(nullptr,2);
  l2norm_kernel<<<MM,64>>>(nullptr,3);
  corr_kernel<<<dim3(MM/64,NN/64),256>>>(1);
  colmax_kernel<<<NN,128>>>(1);
  rowmax_kernel<<<MM/8,256>>>(1);
  pack_kernel<<<MM,NN>>>();
  basem_kernel<<<MM,128>>>(w1_0,b1_0);
  basen_kernel<<<NN,128>>>(wp,w1_0);
  big_kernel<<<NN,128,BIG_SMEM>>>(w1_0,w1_1,b1_1,w1_2,b1_2);
  head_kernel<<<NN,128>>>(wm_0,bm_0,wm_1,bm_1,wm_2,bm_2,out+12);
  pnp_kernel<<<1,NN>>>(out);
}

// round 15
// speedup vs baseline: 1.8304x; 1.4654x over previous
#include <cuda_runtime.h>
#include <cuda_bf16.h>
#include <math.h>

#define NN 256
#define MM 1024
#define CC 64
#define KK 16

__device__ float g_xyz[NN*3];
__device__ float g_rf[MM*CC];
__device__ float g_rfi[MM*3];
__device__ float g_wpn[NN*CC];
__device__ float g_rfn[MM*CC];
__device__ float g_sim1[MM*NN];
__device__ float g_sim2[MM*NN];
__device__ float g_invc1[NN], g_invr1[MM], g_invc2[NN], g_invr2[MM];
__device__ int   g_knn[NN*KK];
__device__ float g_pcf[NN*CC];
__device__ float g_imgf[MM*CC];
__device__ float g_pcn[NN*CC];
__device__ float g_imgn[MM*CC];
__device__ float4 g_simQ[NN*MM];
__device__ float g_basem[MM*128];
__device__ float g_basen[NN*128];
__device__ float g_att[NN*CC];
__device__ float g_corres[NN*3];
__device__ float g_win[NN];
// swizzled bf16 weight images: W1 = w1_1^T [n=64][k=128], W2 = w1_2^T [n=64][k=64]
__device__ __nv_bfloat16 g_W1h[64*128], g_W1l[64*128];
__device__ __nv_bfloat16 g_W2h[64*64],  g_W2l[64*64];

__global__ void prep_kernel(const float* __restrict__ wx, const float* __restrict__ lz,
                            const float* __restrict__ RF3, const float* __restrict__ RF3i){
  int m=blockIdx.x, t=threadIdx.x;
  g_rf[m*CC+t]=RF3[t*MM+m];
  if(t<3) g_rfi[m*3+t]=RF3i[t*MM+m];
  if(m<NN&&t<3) g_xyz[m*3+t]=wx[m*3+t]*lz[m];
}

// swizzled offsets (bytes): XOR 16B-chunk with row low bits
__host__ __device__ __forceinline__ unsigned swz128(int r,int k){ // row = 128 bf16 = 256B
  return (unsigned)r*256u + (((unsigned)k*2u) ^ (((unsigned)r&7u)<<4));
}
__host__ __device__ __forceinline__ unsigned swz64(int r,int k){  // row = 64 bf16 = 128B
  return (unsigned)r*128u + (((unsigned)k*2u) ^ (((unsigned)r&7u)<<4));
}

__global__ void bprep_kernel(const float* __restrict__ w1_1, const float* __restrict__ w1_2){
  int t=threadIdx.x;
  for(int i=t;i<64*128;i+=256){
    int c=i>>7, k=i&127;
    float w=w1_1[k*64+c];
    __nv_bfloat16 hi=__float2bfloat16(w);
    float lo=w-__bfloat162float(hi);
    unsigned o=swz128(c,k)>>1;
    g_W1h[o]=hi; g_W1l[o]=__float2bfloat16(lo);
  }
  for(int i=t;i<64*64;i+=256){
    int c=i>>6, k=i&63;
    float w=w1_2[k*64+c];
    __nv_bfloat16 hi=__float2bfloat16(w);
    float lo=w-__bfloat162float(hi);
    unsigned o=swz64(c,k)>>1;
    g_W2h[o]=hi; g_W2l[o]=__float2bfloat16(lo);
  }
}

__global__ void l2norm_kernel(const float* __restrict__ ext,int sel){
  const float* src; float* dst;
  if(sel==0){src=ext;dst=g_wpn;} else if(sel==1){src=g_rf;dst=g_rfn;}
  else if(sel==2){src=g_pcf;dst=g_pcn;} else {src=g_imgf;dst=g_imgn;}
  int r=blockIdx.x,t=threadIdx.x;
  float v=src[r*CC+t], s=v*v;
  for(int o=16;o;o>>=1) s+=__shfl_down_sync(~0u,s,o);
  __shared__ float sh[2];
  if((t&31)==0) sh[t>>5]=s;
  __syncthreads();
  float n=fmaxf(sqrtf(sh[0]+sh[1]),1e-12f);
  dst[r*CC+t]=v/n;
}

__global__ __launch_bounds__(256) void corr_kernel(int sel){
  const float *A,*B; float* S;
  if(sel==0){A=g_rfn;B=g_wpn;S=g_sim1;} else {A=g_imgn;B=g_pcn;S=g_sim2;}
  __shared__ float As[64][65], Bs[64][65];
  int t=threadIdx.x, tx=t&15, ty=t>>4;
  int m0=blockIdx.x*64, n0=blockIdx.y*64;
  #pragma unroll
  for(int i=0;i<16;i++){int idx=t+i*256,r=idx>>6,c=idx&63;
    As[r][c]=A[(m0+r)*CC+c]; Bs[r][c]=B[(n0+r)*CC+c];}
  __syncthreads();
  float acc[4][4];
  #pragma unroll
  for(int i=0;i<4;i++)
    #pragma unroll
    for(int j=0;j<4;j++) acc[i][j]=0.f;
  #pragma unroll 8
  for(int k=0;k<64;k++){
    float a[4],b[4];
    #pragma unroll
    for(int i=0;i<4;i++){a[i]=As[ty*4+i][k]; b[i]=Bs[tx*4+i][k];}
    #pragma unroll
    for(int i=0;i<4;i++)
      #pragma unroll
      for(int j=0;j<4;j++) acc[i][j]+=a[i]*b[j];
  }
  #pragma unroll
  for(int i=0;i<4;i++)
    #pragma unroll
    for(int j=0;j<4;j++) S[(m0+ty*4+i)*NN+n0+tx*4+j]=acc[i][j];
}

__global__ void colmax_kernel(int sel){
  const float* S=sel?g_sim2:g_sim1; float* ic=sel?g_invc2:g_invc1;
  int n=blockIdx.x, t=threadIdx.x;
  float mx=-1e30f;
  for(int m=t;m<MM;m+=128) mx=fmaxf(mx,S[m*NN+n]);
  for(int o=16;o;o>>=1) mx=fmaxf(mx,__shfl_down_sync(~0u,mx,o));
  __shared__ float sh[4];
  if((t&31)==0) sh[t>>5]=mx;
  __syncthreads();
  if(t==0){
    mx=fmaxf(fmaxf(sh[0],sh[1]),fmaxf(sh[2],sh[3]));
    ic[n]=1.f/(mx+1e-6f);
  }
}
__global__ void rowmax_kernel(int sel){
  const float* S=sel?g_sim2:g_sim1; float* ir=sel?g_invr2:g_invr1;
  int w=threadIdx.x>>5,l=threadIdx.x&31,m=blockIdx.x*8+w;
  float mx=-1e30f;
  for(int n=l;n<NN;n+=32) mx=fmaxf(mx,S[m*NN+n]);
  for(int o=16;o;o>>=1) mx=fmaxf(mx,__shfl_down_sync(~0u,mx,o));
  if(l==0) ir[m]=1.f/(mx+1e-10f);
}

__global__ void knn_kernel(){
  int n=blockIdx.x,t=threadIdx.x;
  __shared__ float sx[NN*3], d2[NN], wm[8];
  __shared__ int wi[8];
  for(int i=t;i<NN*3;i+=256) sx[i]=g_xyz[i];
  __syncthreads();
  float cx=sx[n*3],cy=sx[n*3+1],cz=sx[n*3+2];
  float dx=sx[t*3]-cx,dy=sx[t*3+1]-cy,dz=sx[t*3+2]-cz;
  d2[t]=dx*dx+dy*dy+dz*dz;
  __syncthreads();
  for(int it=0;it<KK;it++){
    float v=d2[t]; int id=t;
    for(int o=16;o;o>>=1){
      float ov=__shfl_down_sync(~0u,v,o); int oi=__shfl_down_sync(~0u,id,o);
      if(ov<v||(ov==v&&oi<id)){v=ov;id=oi;}
    }
    if((t&31)==0){wm[t>>5]=v;wi[t>>5]=id;}
    __syncthreads();
    if(t==0){
      float bv=wm[0];int bi=wi[0];
      for(int w=1;w<8;w++) if(wm[w]<bv||(wm[w]==bv&&wi[w]<bi)){bv=wm[w];bi=wi[w];}
      g_knn[n*KK+it]=bi; d2[bi]=1e38f;
    }
    __syncthreads();
  }
}

#define MLP2_SMEM (15888*4)
__global__ __launch_bounds__(256) void mlp2_kernel(const float* __restrict__ wp,
    const float* __restrict__ w0,const float* __restrict__ b0,
    const float* __restrict__ w1,const float* __restrict__ b1,
    const float* __restrict__ w2,const float* __restrict__ b2){
  extern __shared__ float sm[];
  float* W0=sm; float* W1=W0+4352; float* W2=W1+4096;
  float* B0=W2+4096; float* B1=B0+64; float* B2=B1+64;
  float* IN=B2+64; float* Ha=IN+1088; float* Hb=Ha+1024; float* wk=Hb+1024;
  int n=blockIdx.x,t=threadIdx.x;
  for(int i=t;i<4352;i+=256) W0[i]=w0[i];
  for(int i=t;i<4096;i+=256){W1[i]=w1[i];W2[i]=w2[i];}
  if(t<64){B0[t]=b0[t];B1[t]=b1[t];B2[t]=b2[t];}
  for(int i=t;i<16*68;i+=256){
    int k=i/68,f=i%68,nb=g_knn[n*KK+k]; float val;
    if(f<64) val=wp[nb*CC+f];
    else if(f<67) val=g_xyz[nb*3+(f-64)]-g_xyz[n*3+(f-64)];
    else{
      float dx=g_xyz[nb*3]-g_xyz[n*3],dy=g_xyz[nb*3+1]-g_xyz[n*3+1],dz=g_xyz[nb*3+2]-g_xyz[n*3+2];
      val=sqrtf(dx*dx+dy*dy+dz*dz);
    }
    IN[k*68+f]=val;
  }
  __syncthreads();
  for(int o=t;o<1024;o+=256){int k=o>>6,j=o&63; float s=B0[j];
    #pragma unroll 4
    for(int i=0;i<68;i++) s+=IN[k*68+i]*W0[i*64+j];
    Ha[o]=fmaxf(s,0.f);}
  __syncthreads();
  for(int o=t;o<1024;o+=256){int k=o>>6,j=o&63; float s=B1[j];
    #pragma unroll 4
    for(int i=0;i<64;i++) s+=Ha[k*64+i]*W1[i*64+j];
    Hb[o]=fmaxf(s,0.f);}
  __syncthreads();
  for(int o=t;o<1024;o+=256){int k=o>>6,j=o&63; float s=B2[j];
    #pragma unroll 4
    for(int i=0;i<64;i++) s+=Hb[k*64+i]*W2[i*64+j];
    Ha[o]=fmaxf(s,0.f);}
  __syncthreads();
  if(t<16){float mx=-1e30f; for(int j=0;j<64;j++) mx=fmaxf(mx,Ha[t*64+j]); wk[t]=mx;}
  __syncthreads();
  if(t==0){
    float mx=-1e30f; for(int k=0;k<16;k++) mx=fmaxf(mx,wk[k]);
    float s=0.f; for(int k=0;k<16;k++){wk[k]=expf(wk[k]-mx);s+=wk[k];}
    float inv=1.f/s; for(int k=0;k<16;k++) wk[k]*=inv;
  }
  __syncthreads();
  if(t<64){float s=0.f; for(int k=0;k<16;k++) s+=wk[k]*IN[k*68+t]; g_pcf[n*CC+t]=s;}
}

#define MLP3_SMEM (14443*4)
__global__ __launch_bounds__(256) void mlp3_kernel(
    const float* __restrict__ w0,const float* __restrict__ b0,
    const float* __restrict__ w1,const float* __restrict__ b1,
    const float* __restrict__ w2,const float* __restrict__ b2){
  extern __shared__ float sm[];
  float* W0=sm; float* W1=W0+4288; float* W2=W1+4096;
  float* B0=W2+4096; float* B1=B0+64; float* B2=B1+64;
  float* IN=B2+64; float* Ha=IN+603; float* Hb=Ha+576; float* wk=Hb+576;
  int m=blockIdx.x,t=threadIdx.x,y=m>>5,x=m&31;
  for(int i=t;i<4288;i+=256) W0[i]=w0[i];
  for(int i=t;i<4096;i+=256){W1[i]=w1[i];W2[i]=w2[i];}
  if(t<64){B0[t]=b0[t];B1[t]=b1[t];B2[t]=b2[t];}
  for(int i=t;i<9*67;i+=256){
    int k=i/67,f=i%67,dy=k/3-1,dx=k%3-1,yy=y+dy,xx=x+dx;
    float val=0.f;
    if(yy>=0&&yy<32&&xx>=0&&xx<32){int mm=yy*32+xx; val=(f<3)?g_rfi[mm*3+f]:g_rf[mm*CC+f-3];}
    IN[k*67+f]=val;
  }
  __syncthreads();
  for(int o=t;o<576;o+=256){int k=o>>6,j=o&63; float s=B0[j];
    #pragma unroll 4
    for(int i=0;i<67;i++) s+=IN[k*67+i]*W0[i*64+j];
    Ha[o]=fmaxf(s,0.f);}
  __syncthreads();
  for(int o=t;o<576;o+=256){int k=o>>6,j=o&63; float s=B1[j];
    #pragma unroll 4
    for(int i=0;i<64;i++) s+=Ha[k*64+i]*W1[i*64+j];
    Hb[o]=fmaxf(s,0.f);}
  __syncthreads();
  for(int o=t;o<576;o+=256){int k=o>>6,j=o&63; float s=B2[j];
    #pragma unroll 4
    for(int i=0;i<64;i++) s+=Hb[k*64+i]*W2[i*64+j];
    Ha[o]=fmaxf(s,0.f);}
  __syncthreads();
  if(t<9){float mx=-1e30f; for(int j=0;j<64;j++) mx=fmaxf(mx,Ha[t*64+j]); wk[t]=mx;}
  __syncthreads();
  if(t==0){
    float mx=-1e30f; for(int k=0;k<9;k++) mx=fmaxf(mx,wk[k]);
    float s=0.f; for(int k=0;k<9;k++){wk[k]=expf(wk[k]-mx);s+=wk[k];}
    float inv=1.f/s; for(int k=0;k<9;k++) wk[k]*=inv;
  }
  __syncthreads();
  if(t<64){float s=0.f; for(int k=0;k<9;k++) s+=wk[k]*IN[k*67+3+t]; g_imgf[m*CC+t]=s;}
}

// transpose-pack via smem tile: coalesced reads AND writes
__global__ __launch_bounds__(256) void pack_kernel(){
  __shared__ float s1[32][33], s2[32][33];
  int m0=blockIdx.x*32, n0=blockIdx.y*32, t=threadIdx.x;
  #pragma unroll
  for(int i=0;i<4;i++){
    int idx=t+i*256, mr=idx>>5, nc=idx&31;
    s1[mr][nc]=g_sim1[(m0+mr)*NN+n0+nc];
    s2[mr][nc]=g_sim2[(m0+mr)*NN+n0+nc];
  }
  __syncthreads();
  #pragma unroll
  for(int i=0;i<4;i++){
    int idx=t+i*256, nr=idx>>5, mc=idx&31;
    int n=n0+nr, m=m0+mc;
    float v1=s1[mc][nr], v2=s2[mc][nr];
    float4 q; q.x=v1*g_invc1[n]; q.y=v1*g_invr1[m]; q.z=v2*g_invc2[n]; q.w=v2*g_invr2[m];
    g_simQ[n*MM+m]=q;
  }
}

__global__ void basem_kernel(const float* __restrict__ w1_0,const float* __restrict__ b1_0){
  int m=blockIdx.x,t=threadIdx.x;
  __shared__ float in[67];
  if(t<3) in[t]=g_rfi[m*3+t]; else if(t<67) in[t]=g_rf[m*CC+t-3];
  __syncthreads();
  float acc=b1_0[t];
  #pragma unroll
  for(int i=0;i<3;i++) acc+=in[i]*w1_0[(3+i)*128+t];
  #pragma unroll 4
  for(int i=0;i<64;i++) acc+=in[3+i]*w1_0[(70+i)*128+t];
  g_basem[m*128+t]=acc;
}
__global__ void basen_kernel(const float* __restrict__ wp,const float* __restrict__ w1_0){
  int n=blockIdx.x,t=threadIdx.x;
  __shared__ float in[67];
  if(t<3) in[t]=g_xyz[n*3+t]; else if(t<67) in[t]=wp[n*CC+t-3];
  __syncthreads();
  float acc=0.f;
  #pragma unroll
  for(int i=0;i<3;i++) acc+=in[i]*w1_0[i*128+t];
  #pragma unroll 4
  for(int i=0;i<64;i++) acc+=in[3+i]*w1_0[(6+i)*128+t];
  g_basen[n*128+t]=acc;
}

// =============== big kernel: mma.sync bf16 hi/lo ===============
#define SB_A1H 0
#define SB_A1L 16384
#define SB_A2H 32768
#define SB_A2L 40960
#define SB_W1H 49152
#define SB_W1L 65536
#define SB_W2H 81920
#define SB_W2L 90112
#define SB_WS  98304
#define SB_BN  100352
#define SB_BA  100864
#define SB_BB  101120
#define SB_SQ  101376
#define SB_RM  102400
#define SB_EE  102656
#define SB_SC  102912
#define SB_AS  103936
#define SB_CO  104192
#define SB_MS  104208
#define SB_AL  104212
#define SB_ZS  104216
#define BIG_SMEM 104224
// FS (fp32 64x68) overlays A1H+A1L (32KB)

__device__ __forceinline__ unsigned smem_u32(const void* p){
  unsigned a;
  asm("{ .reg .u64 tmp; cvta.to.shared.u64 tmp, %1; cvt.u32.u64 %0, tmp; }":"=r"(a):"l"(p));
  return a;
}
#define LDM4(r0,r1,r2,r3,addr) \
  asm volatile("ldmatrix.sync.aligned.m8n8.x4.shared.b16 {%0,%1,%2,%3},[%4];" \
    : "=r"(r0),"=r"(r1),"=r"(r2),"=r"(r3) : "r"(addr))
#define MMA16816(d,a0,a1,a2,a3,b0,b1) \
  asm volatile("mma.sync.aligned.m16n8k16.row.col.f32.bf16.bf16.f32 " \
    "{%0,%1,%2,%3},{%4,%5,%6,%7},{%8,%9},{%0,%1,%2,%3};" \
    : "+f"((d)[0]),"+f"((d)[1]),"+f"((d)[2]),"+f"((d)[3]) \
    : "r"(a0),"r"(a1),"r"(a2),"r"(a3),"r"(b0),"r"(b1))

__global__ __launch_bounds__(256,2) void big_kernel(
    const float* __restrict__ w1_0,const float* __restrict__ b1_1,const float* __restrict__ b1_2){
  extern __shared__ char smc[];
  unsigned sb=smem_u32(smc);
  int t=threadIdx.x, n=blockIdx.x;
  int wid=t>>5, lane=t&31;
  int mg=wid&3, ng=wid>>2;
  float* WS=(float*)(smc+SB_WS);
  float* BN=(float*)(smc+SB_BN);
  float* BA=(float*)(smc+SB_BA);
  float* BB=(float*)(smc+SB_BB);
  float4* SQ=(float4*)(smc+SB_SQ);
  float* RM=(float*)(smc+SB_RM);
  float* EE=(float*)(smc+SB_EE);
  float* SC=(float*)(smc+SB_SC);
  float* AS=(float*)(smc+SB_AS);
  float* CO=(float*)(smc+SB_CO);
  float* MS=(float*)(smc+SB_MS);
  float* AL=(float*)(smc+SB_AL);
  float* ZS=(float*)(smc+SB_ZS);
  float* FS=(float*)(smc+SB_A1H);   // 64x68 fp32 overlay

  { // weight images -> smem (linear 16B copies of pre-swizzled images)
    uint4* d1=(uint4*)(smc+SB_W1H); const uint4* s1=(const uint4*)g_W1h;
    uint4* d2=(uint4*)(smc+SB_W1L); const uint4* s2=(const uint4*)g_W1l;
    for(int i=t;i<1024;i+=256){ d1[i]=s1[i]; d2[i]=s2[i]; }
    uint4* d3=(uint4*)(smc+SB_W2H); const uint4* s3=(const uint4*)g_W2h;
    uint4* d4=(uint4*)(smc+SB_W2L); const uint4* s4=(const uint4*)g_W2l;
    for(int i=t;i<512;i+=256){ d3[i]=s3[i]; d4[i]=s4[i]; }
  }
  for(int i=t;i<512;i+=256) WS[i]=w1_0[134*128+i];
  if(t<128) BN[t]=g_basen[n*128+t];
  if(t<64){ BA[t]=b1_1[t]; BB[t]=b1_2[t]; AS[t]=0.f; }
  if(t<4) CO[t]=0.f;
  if(t==0){ ZS[0]=0.f; MS[0]=-1e30f; }
  __syncthreads();

  // per-lane fragment geometry
  int arow = mg*16 + (lane&15);            // A frag row for ldmatrix
  unsigned axor = ((unsigned)(arow&7))<<4;
  int bg = lane>>3;                         // 0..3 group
  int brow = ng*32 + (lane&7) + (bg&1)*8;   // B rows (n) for first 16 cols
  unsigned bxor = ((unsigned)(brow&7))<<4;
  unsigned akadd = ((unsigned)(lane>>4))*16u;   // A k-chunk byte add
  unsigned bkadd = ((unsigned)(bg>>1))*16u;     // B k-chunk byte add
  int erow = mg*16 + (lane>>2);                 // epilogue rows erow, erow+8
  int ecol0 = (lane&3)*2;

  int c_ = t&127, half_=t>>7;   // phase A mapping

  for(int tile=0;tile<16;tile++){
    int m0=tile*64;
    if(t<64) SQ[t]=g_simQ[n*MM+m0+t];
    __syncthreads();
    // ---- phase A: H1 = relu(basem+basen+sim4@WS) -> bf16 hi/lo swizzled ----
    #pragma unroll 4
    for(int i=0;i<32;i++){
      int r=half_*32+i;
      float4 q=SQ[r];
      float h=g_basem[(m0+r)*128+c_]+BN[c_]
             +q.x*WS[c_]+q.y*WS[128+c_]+q.z*WS[256+c_]+q.w*WS[384+c_];
      h=fmaxf(h,0.f);
      __nv_bfloat16 hi=__float2bfloat16(h);
      float lo=h-__bfloat162float(hi);
      unsigned o=swz128(r,c_);
      *(__nv_bfloat16*)(smc+SB_A1H+o)=hi;
      *(__nv_bfloat16*)(smc+SB_A1L+o)=__float2bfloat16(lo);
    }
    __syncthreads();
    // ---- layer 1: 64x64 += A1[64x128] @ W1^T, hi/lo ----
    float d1[4][4];
    #pragma unroll
    for(int j=0;j<4;j++){d1[j][0]=0;d1[j][1]=0;d1[j][2]=0;d1[j][3]=0;}
    #pragma unroll
    for(int ks=0;ks<8;ks++){
      unsigned ak2=ks*32u+akadd, bk2=ks*32u+bkadd;
      unsigned ah0,ah1,ah2,ah3, al0,al1,al2,al3;
      LDM4(ah0,ah1,ah2,ah3, sb+SB_A1H+(unsigned)arow*256u+(ak2^axor));
      LDM4(al0,al1,al2,al3, sb+SB_A1L+(unsigned)arow*256u+(ak2^axor));
      unsigned bh0,bh1,bh2,bh3, bh4,bh5,bh6,bh7;
      unsigned bl0,bl1,bl2,bl3, bl4,bl5,bl6,bl7;
      unsigned boff1=(unsigned)brow*256u+(bk2^bxor);
      unsigned boff2=(unsigned)(brow+16)*256u+(bk2^bxor);
      LDM4(bh0,bh1,bh2,bh3, sb+SB_W1H+boff1);
      LDM4(bh4,bh5,bh6,bh7, sb+SB_W1H+boff2);
      LDM4(bl0,bl1,bl2,bl3, sb+SB_W1L+boff1);
      LDM4(bl4,bl5,bl6,bl7, sb+SB_W1L+boff2);
      MMA16816(d1[0],ah0,ah1,ah2,ah3,bh0,bh2);
      MMA16816(d1[1],ah0,ah1,ah2,ah3,bh1,bh3);
      MMA16816(d1[2],ah0,ah1,ah2,ah3,bh4,bh6);
      MMA16816(d1[3],ah0,ah1,ah2,ah3,bh5,bh7);
      MMA16816(d1[0],ah0,ah1,ah2,ah3,bl0,bl2);
      MMA16816(d1[1],ah0,ah1,ah2,ah3,bl1,bl3);
      MMA16816(d1[2],ah0,ah1,ah2,ah3,bl4,bl6);
      MMA16816(d1[3],ah0,ah1,ah2,ah3,bl5,bl7);
      MMA16816(d1[0],al0,al1,al2,al3,bh0,bh2);
      MMA16816(d1[1],al0,al1,al2,al3,bh1,bh3);
      MMA16816(d1[2],al0,al1,al2,al3,bh4,bh6);
      MMA16816(d1[3],al0,al1,al2,al3,bh5,bh7);
    }
    // ---- epilogue 1: bias+relu -> A2 hi/lo ----
    #pragma unroll
    for(int j=0;j<4;j++){
      int cj=ng*32+j*8+ecol0;
      float b0=BA[cj], b1=BA[cj+1];
      float v00=fmaxf(d1[j][0]+b0,0.f), v01=fmaxf(d1[j][1]+b1,0.f);
      float v10=fmaxf(d1[j][2]+b0,0.f), v11=fmaxf(d1[j][3]+b1,0.f);
      __nv_bfloat162 h0, h1, l0, l1;
      h0.x=__float2bfloat16(v00); h0.y=__float2bfloat16(v01);
      h1.x=__float2bfloat16(v10); h1.y=__float2bfloat16(v11);
      l0.x=__float2bfloat16(v00-__bfloat162float(h0.x)); l0.y=__float2bfloat16(v01-__bfloat162float(h0.y));
      l1.x=__float2bfloat16(v10-__bfloat162float(h1.x)); l1.y=__float2bfloat16(v11-__bfloat162float(h1.y));
      unsigned o1=swz64(erow,cj), o2=swz64(erow+8,cj);
      *(__nv_bfloat162*)(smc+SB_A2H+o1)=h0;
      *(__nv_bfloat162*)(smc+SB_A2H+o2)=h1;
      *(__nv_bfloat162*)(smc+SB_A2L+o1)=l0;
      *(__nv_bfloat162*)(smc+SB_A2L+o2)=l1;
    }
    __syncthreads();
    // ---- layer 2: 64x64 += A2[64x64] @ W2^T ----
    float d2[4][4];
    #pragma unroll
    for(int j=0;j<4;j++){d2[j][0]=0;d2[j][1]=0;d2[j][2]=0;d2[j][3]=0;}
    #pragma unroll
    for(int ks=0;ks<4;ks++){
      unsigned ak2=ks*32u+akadd, bk2=ks*32u+bkadd;
      unsigned ah0,ah1,ah2,ah3, al0,al1,al2,al3;
      LDM4(ah0,ah1,ah2,ah3, sb+SB_A2H+(unsigned)arow*128u+(ak2^axor));
      LDM4(al0,al1,al2,al3, sb+SB_A2L+(unsigned)arow*128u+(ak2^axor));
      unsigned bh0,bh1,bh2,bh3, bh4,bh5,bh6,bh7;
      unsigned bl0,bl1,bl2,bl3, bl4,bl5,bl6,bl7;
      unsigned boff1=(unsigned)brow*128u+(bk2^bxor);
      unsigned boff2=(unsigned)(brow+16)*128u+(bk2^bxor);
      LDM4(bh0,bh1,bh2,bh3, sb+SB_W2H+boff1);
      LDM4(bh4,bh5,bh6,bh7, sb+SB_W2H+boff2);
      LDM4(bl0,bl1,bl2,bl3, sb+SB_W2L+boff1);
      LDM4(bl4,bl5,bl6,bl7, sb+SB_W2L+boff2);
      MMA16816(d2[0],ah0,ah1,ah2,ah3,bh0,bh2);
      MMA16816(d2[1],ah0,ah1,ah2,ah3,bh1,bh3);
      MMA16816(d2[2],ah0,ah1,ah2,ah3,bh4,bh6);
      MMA16816(d2[3],ah0,ah1,ah2,ah3,bh5,bh7);
      MMA16816(d2[0],ah0,ah1,ah2,ah3,bl0,bl2);
      MMA16816(d2[1],ah0,ah1,ah2,ah3,bl1,bl3);
      MMA16816(d2[2],ah0,ah1,ah2,ah3,bl4,bl6);
      MMA16816(d2[3],ah0,ah1,ah2,ah3,bl5,bl7);
      MMA16816(d2[0],al0,al1,al2,al3,bh0,bh2);
      MMA16816(d2[1],al0,al1,al2,al3,bh1,bh3);
      MMA16816(d2[2],al0,al1,al2,al3,bh4,bh6);
      MMA16816(d2[3],al0,al1,al2,al3,bh5,bh7);
    }
    __syncthreads();   // all A1 reads done before FS (overlay) writes
    // ---- epilogue 2: F = relu(D2+BB) -> FS fp32 ----
    #pragma unroll
    for(int j=0;j<4;j++){
      int cj=ng*32+j*8+ecol0;
      FS[erow*68+cj]    =fmaxf(d2[j][0]+BB[cj],0.f);
      FS[erow*68+cj+1]  =fmaxf(d2[j][1]+BB[cj+1],0.f);
      FS[(erow+8)*68+cj]  =fmaxf(d2[j][2]+BB[cj],0.f);
      FS[(erow+8)*68+cj+1]=fmaxf(d2[j][3]+BB[cj+1],0.f);
    }
    __syncthreads();
    // ---- phase D: online softmax over 64-row tile ----
    if(t<64){
      float mx=-1e30f;
      #pragma unroll 8
      for(int c=0;c<64;c++) mx=fmaxf(mx,FS[t*68+c]);
      RM[t]=mx;
    }
    __syncthreads();
    if(t<32){
      float v=fmaxf(RM[t],RM[t+32]);
      for(int o=16;o;o>>=1) v=fmaxf(v,__shfl_down_sync(~0u,v,o));
      if(t==0){ float oldM=MS[0], nM=fmaxf(oldM,v); AL[0]=expf(oldM-nM); MS[0]=nM; }
    }
    __syncthreads();
    if(t<64) EE[t]=expf(RM[t]-MS[0]);
    __syncthreads();
    {
      int c=t&63, q=t>>6;
      float s=0.f;
      #pragma unroll 4
      for(int r=q*16;r<q*16+16;r++) s+=EE[r]*FS[r*68+c];
      SC[t]=s;
    }
    __syncthreads();
    float alpha=AL[0];
    if(t<64) AS[t]=AS[t]*alpha+SC[t]+SC[64+t]+SC[128+t]+SC[192+t];
    else if(t<96){
      int l=t&31; float a=0.f;
      for(int r=l;r<64;r+=32) a+=EE[r]*g_rfi[(m0+r)*3+0];
      for(int o=16;o;o>>=1) a+=__shfl_down_sync(~0u,a,o);
      if(l==0) CO[0]=CO[0]*alpha+a;
    } else if(t<128){
      int l=t&31; float a=0.f;
      for(int r=l;r<64;r+=32) a+=EE[r]*g_rfi[(m0+r)*3+1];
      for(int o=16;o;o>>=1) a+=__shfl_down_sync(~0u,a,o);
      if(l==0) CO[1]=CO[1]*alpha+a;
    } else if(t<160){
      int l=t&31; float a=0.f;
      for(int r=l;r<64;r+=32) a+=EE[r]*g_rfi[(m0+r)*3+2];
      for(int o=16;o;o>>=1) a+=__shfl_down_sync(~0u,a,o);
      if(l==0) CO[2]=CO[2]*alpha+a;
    } else if(t<192){
      int l=t&31; float z=0.f;
      for(int r=l;r<64;r+=32) z+=EE[r];
      for(int o=16;o;o>>=1) z+=__shfl_down_sync(~0u,z,o);
      if(l==0) ZS[0]=ZS[0]*alpha+z;
    }
    __syncthreads();
  }
  if(t<64) g_att[n*CC+t]=AS[t]/ZS[0];
  else if(t<67) g_corres[n*3+(t-64)]=CO[t-64]/ZS[0];
}

__global__ void head_kernel(const float* __restrict__ wm0,const float* __restrict__ bm0,
    const float* __restrict__ wm1,const float* __restrict__ bm1,
    const float* __restrict__ wm2,const float* __restrict__ bm2,float* __restrict__ outw){
  int n=blockIdx.x,t=threadIdx.x;
  __shared__ float a[64],h1[64],h2[128];
  if(t<64) a[t]=g_att[n*CC+t];
  __syncthreads();
  if(t<64){
    float s=bm0[t];
    #pragma unroll 4
    for(int k=0;k<64;k++) s+=a[k]*wm0[k*64+t];
    h1[t]=fmaxf(s,0.f);
  }
  __syncthreads();
  {
    float s=bm1[t];
    #pragma unroll 4
    for(int k=0;k<64;k++) s+=h1[k]*wm1[k*128+t];
    h2[t]=fmaxf(s,0.f);
  }
  __syncthreads();
  if(t==0){
    float l0=bm2[0],l1=bm2[1];
    for(int k=0;k<128;k++){l0+=h2[k]*wm2[k*2];l1+=h2[k]*wm2[k*2+1];}
    float mx=fmaxf(l0,l1),e0=expf(l0-mx),e1=expf(l1-mx),inv=1.f/(e0+e1);
    outw[n*2]=e0*inv; outw[n*2+1]=e1*inv;
    g_win[n]=(l1>l0)?1.f:0.f;
  }
}

__device__ float brs(float v,float* red){
  int t=threadIdx.x;
  red[t]=v; __syncthreads();
  for(int s=128;s>0;s>>=1){ if(t<s) red[t]+=red[t+s]; __syncthreads(); }
  float r=red[0]; __syncthreads();
  return r;
}

__global__ void pnp_kernel(float* __restrict__ out){
  __shared__ float red[256];
  int t=threadIdx.x;
  float w=g_win[t];
  float sx=g_xyz[t*3],sy=g_xyz[t*3+1],sz=g_xyz[t*3+2];
  float u=g_corres[t*3],v=g_corres[t*3+1];
  float dx=u*sz,dy=v*sz,dz=sz;
  float sw=brs(w,red);
  float wn=w/(sw+1e-8f);
  float scx=brs(wn*sx,red),scy=brs(wn*sy,red),scz=brs(wn*sz,red);
  float dcx=brs(wn*dx,red),dcy=brs(wn*dy,red),dcz=brs(wn*dz,red);
  float ax=sx-scx,ay=sy-scy,az=sz-scz;
  float bx=dx-dcx,by=dy-dcy,bz=dz-dcz;
  float hm[9];
  hm[0]=brs(wn*ax*bx,red);hm[1]=brs(wn*ax*by,red);hm[2]=brs(wn*ax*bz,red);
  hm[3]=brs(wn*ay*bx,red);hm[4]=brs(wn*ay*by,red);hm[5]=brs(wn*ay*bz,red);
  hm[6]=brs(wn*az*bx,red);hm[7]=brs(wn*az*by,red);hm[8]=brs(wn*az*bz,red);
  if(t==0){
    double h[3][3]={{hm[0],hm[1],hm[2]},{hm[3],hm[4],hm[5]},{hm[6],hm[7],hm[8]}};
    double A[3][3],V[3][3]={{1,0,0},{0,1,0},{0,0,1}};
    for(int i=0;i<3;i++)for(int j=0;j<3;j++){double s=0;for(int k=0;k<3;k++)s+=h[k][i]*h[k][j];A[i][j]=s;}
    const int P[3]={0,0,1},Q[3]={1,2,2};
    for(int sweep=0;sweep<20;sweep++)
      for(int r=0;r<3;r++){
        int p=P[r],qq=Q[r];
        double apq=A[p][qq];
        if(fabs(apq)<1e-300) continue;
        double tau=(A[qq][qq]-A[p][p])/(2.0*apq);
        double tt=((tau>=0)?1.0:-1.0)/(fabs(tau)+sqrt(1.0+tau*tau));
        double c=1.0/sqrt(1.0+tt*tt),s=tt*c;
        for(int k=0;k<3;k++){double a1=A[k][p],a2=A[k][qq];A[k][p]=c*a1-s*a2;A[k][qq]=s*a1+c*a2;}
        for(int k=0;k<3;k++){double a1=A[p][k],a2=A[qq][k];A[p][k]=c*a1-s*a2;A[qq][k]=s*a1+c*a2;}
        for(int k=0;k<3;k++){double v1=V[k][p],v2=V[k][qq];V[k][p]=c*v1-s*v2;V[k][qq]=s*v1+c*v2;}
      }
    double lam[3]={A[0][0],A[1][1],A[2][2]};
    int o[3]={0,1,2};
    if(lam[o[0]]<lam[o[1]]){int x=o[0];o[0]=o[1];o[1]=x;}
    if(lam[o[1]]<lam[o[2]]){int x=o[1];o[1]=o[2];o[2]=x;}
    if(lam[o[0]]<lam[o[1]]){int x=o[0];o[0]=o[1];o[1]=x;}
    double vv[3][3],uu[3][3],sg[3];
    for(int i=0;i<3;i++){
      sg[i]=sqrt(fmax(lam[o[i]],0.0));
      for(int k=0;k<3;k++) vv[i][k]=V[k][o[i]];
    }
    for(int i=0;i<2;i++){
      for(int j=0;j<3;j++){double s=0;for(int k=0;k<3;k++)s+=h[j][k]*vv[i][k];uu[i][j]=s/fmax(sg[i],1e-300);}
    }
    if(sg[2]>1e-9*sg[0]){
      for(int j=0;j<3;j++){double s=0;for(int k=0;k<3;k++)s+=h[j][k]*vv[2][k];uu[2][j]=s/sg[2];}
    } else {
      uu[2][0]=uu[0][1]*uu[1][2]-uu[0][2]*uu[1][1];
      uu[2][1]=uu[0][2]*uu[1][0]-uu[0][0]*uu[1][2];
      uu[2][2]=uu[0][0]*uu[1][1]-uu[0][1]*uu[1][0];
    }
    double detV=vv[0][0]*(vv[1][1]*vv[2][2]-vv[1][2]*vv[2][1])
               -vv[0][1]*(vv[1][0]*vv[2][2]-vv[1][2]*vv[2][0])
               +vv[0][2]*(vv[1][0]*vv[2][1]-vv[1][1]*vv[2][0]);
    double detU=uu[0][0]*(uu[1][1]*uu[2][2]-uu[1][2]*uu[2][1])
               -uu[0][1]*(uu[1][0]*uu[2][2]-uu[1][2]*uu[2][0])
               +uu[0][2]*(uu[1][0]*uu[2][1]-uu[1][1]*uu[2][0]);
    double d=detV*detU;
    double R[3][3];
    for(int i=0;i<3;i++)for(int j=0;j<3;j++)
      R[i][j]=vv[0][i]*uu[0][j]+vv[1][i]*uu[1][j]+d*vv[2][i]*uu[2][j];
    double sc[3]={scx,scy,scz},dc[3]={dcx,dcy,dcz};
    for(int i=0;i<3;i++){
      for(int j=0;j<3;j++) out[i*3+j]=(float)R[i][j];
      double s=0; for(int j=0;j<3;j++) s+=R[i][j]*sc[j];
      out[9+i]=(float)(dc[i]-s);
    }
  }
}

extern "C" void kernel_launch(void* const* d_in, const int* in_sizes, int n_in,
                              void* d_out, int out_size){
  const float* wx  =(const float*)d_in[0];
  const float* wp  =(const float*)d_in[1];
  const float* RF3 =(const float*)d_in[2];
  const float* RF3i=(const float*)d_in[3];
  const float* lz  =(const float*)d_in[4];
  const float* w2_0=(const float*)d_in[5];  const float* b2_0=(const float*)d_in[6];
  const float* w2_1=(const float*)d_in[7];  const float* b2_1=(const float*)d_in[8];
  const float* w2_2=(const float*)d_in[9];  const float* b2_2=(const float*)d_in[10];
  const float* w3_0=(const float*)d_in[11]; const float* b3_0=(const float*)d_in[12];
  const float* w3_1=(const float*)d_in[13]; const float* b3_1=(const float*)d_in[14];
  const float* w3_2=(const float*)d_in[15]; const float* b3_2=(const float*)d_in[16];
  const float* w1_0=(const float*)d_in[17]; const float* b1_0=(const float*)d_in[18];
  const float* w1_1=(const float*)d_in[19]; const float* b1_1=(const float*)d_in[20];
  const float* w1_2=(const float*)d_in[21]; const float* b1_2=(const float*)d_in[22];
  const float* wm_0=(const float*)d_in[23]; const float* bm_0=(const float*)d_in[24];
  const float* wm_1=(const float*)d_in[25]; const float* bm_1=(const float*)d_in[26];
  const float* wm_2=(const float*)d_in[27]; const float* bm_2=(const float*)d_in[28];
  float* out=(float*)d_out;

  cudaFuncSetAttribute(mlp2_kernel, cudaFuncAttributeMaxDynamicSharedMemorySize, MLP2_SMEM);
  cudaFuncSetAttribute(mlp3_kernel, cudaFuncAttributeMaxDynamicSharedMemorySize, MLP3_SMEM);
  cudaFuncSetAttribute(big_kernel,  cudaFuncAttributeMaxDynamicSharedMemorySize, BIG_SMEM);

  prep_kernel<<<MM,64>>>(wx,lz,RF3,RF3i);
  bprep_kernel<<<1,256>>>(w1_1,w1_2);
  l2norm_kernel<<<NN,64>>>(wp,0);
  l2norm_kernel<<<MM,64>>>(nullptr,1);
  corr_kernel<<<dim3(MM/64,NN/64),256>>>(0);
  colmax_kernel<<<NN,128>>>(0);
  rowmax_kernel<<<MM/8,256>>>(0);
  knn_kernel<<<NN,256>>>();
  mlp2_kernel<<<NN,256,MLP2_SMEM>>>(wp,w2_0,b2_0,w2_1,b2_1,w2_2,b2_2);
  mlp3_kernel<<<MM,256,MLP3_SMEM>>>(w3_0,b3_0,w3_1,b3_1,w3_2,b3_2);
  l2norm_kernel<<<NN,64>>>(nullptr,2);
  l2norm_kernel<<<MM,64>>>(nullptr,3);
  corr_kernel<<<dim3(MM/64,NN/64),256>>>(1);
  colmax_kernel<<<NN,128>>>(1);
  rowmax_kernel<<<MM/8,256>>>(1);
  pack_kernel<<<dim3(MM/32,NN/32),256>>>();
  basem_kernel<<<MM,128>>>(w1_0,b1_0);
  basen_kernel<<<NN,128>>>(wp,w1_0);
  big_kernel<<<NN,256,BIG_SMEM>>>(w1_0,b1_1,b1_2);
  head_kernel<<<NN,128>>>(wm_0,bm_0,wm_1,bm_1,wm_2,bm_2,out+12);
  pnp_kernel<<<1,NN>>>(out);
}

// round 16
// speedup vs baseline: 1.9197x; 1.0488x over previous
#include <cuda_runtime.h>
#include <cuda_bf16.h>
#include <math.h>

#define NN 256
#define MM 1024
#define CC 64
#define KK 16

__device__ float g_xyz[NN*3];
__device__ float g_rf[MM*CC];
__device__ float g_rfi[MM*3];
__device__ float g_wpn[NN*CC];
__device__ float g_rfn[MM*CC];
__device__ float g_sim1[MM*NN];
__device__ float g_sim2[MM*NN];
__device__ float g_invc1[NN], g_invr1[MM], g_invc2[NN], g_invr2[MM];
__device__ int   g_knn[NN*KK];
__device__ float g_pcn[NN*CC];
__device__ float g_imgn[MM*CC];
__device__ float4 g_simQ[NN*MM];
__device__ float g_basem[MM*128];
__device__ float g_basen[NN*128];
__device__ float g_att[NN*CC];
__device__ float g_corres[NN*3];
__device__ float g_win[NN];
__device__ __nv_bfloat16 g_W1h[64*128], g_W1l[64*128];
__device__ __nv_bfloat16 g_W2h[64*64],  g_W2l[64*64];

__host__ __device__ __forceinline__ unsigned swz128(int r,int k){
  return (unsigned)r*256u + (((unsigned)k*2u) ^ (((unsigned)r&7u)<<4));
}
__host__ __device__ __forceinline__ unsigned swz64(int r,int k){
  return (unsigned)r*128u + (((unsigned)k*2u) ^ (((unsigned)r&7u)<<4));
}

// fused: rf transpose + rfn norm + wpn norm + xyz
__global__ void prep_kernel(const float* __restrict__ wx, const float* __restrict__ lz,
                            const float* __restrict__ RF3, const float* __restrict__ RF3i,
                            const float* __restrict__ wp){
  int m=blockIdx.x, t=threadIdx.x;   // 1024 x 64
  __shared__ float sh[2], sh2[2];
  float rv=RF3[t*MM+m];
  g_rf[m*CC+t]=rv;
  if(t<3) g_rfi[m*3+t]=RF3i[t*MM+m];
  float s=rv*rv;
  for(int o=16;o;o>>=1) s+=__shfl_down_sync(~0u,s,o);
  if((t&31)==0) sh[t>>5]=s;
  __syncthreads();
  float nrm=fmaxf(sqrtf(sh[0]+sh[1]),1e-12f);
  g_rfn[m*CC+t]=rv/nrm;
  if(m<NN){
    if(t<3) g_xyz[m*3+t]=wx[m*3+t]*lz[m];
    float wv=wp[m*CC+t];
    float s2=wv*wv;
    for(int o=16;o;o>>=1) s2+=__shfl_down_sync(~0u,s2,o);
    if((t&31)==0) sh2[t>>5]=s2;
    __syncthreads();
    float n2=fmaxf(sqrtf(sh2[0]+sh2[1]),1e-12f);
    g_wpn[m*CC+t]=wv/n2;
  }
}

__global__ void bprep_kernel(const float* __restrict__ w1_1, const float* __restrict__ w1_2){
  int t=threadIdx.x;
  for(int i=t;i<64*128;i+=256){
    int c=i>>7, k=i&127;
    float w=w1_1[k*64+c];
    __nv_bfloat16 hi=__float2bfloat16(w);
    float lo=w-__bfloat162float(hi);
    unsigned o=swz128(c,k)>>1;
    g_W1h[o]=hi; g_W1l[o]=__float2bfloat16(lo);
  }
  for(int i=t;i<64*64;i+=256){
    int c=i>>6, k=i&63;
    float w=w1_2[k*64+c];
    __nv_bfloat16 hi=__float2bfloat16(w);
    float lo=w-__bfloat162float(hi);
    unsigned o=swz64(c,k)>>1;
    g_W2h[o]=hi; g_W2l[o]=__float2bfloat16(lo);
  }
}

__global__ __launch_bounds__(256) void corr_kernel(int sel){
  const float *A,*B; float* S;
  if(sel==0){A=g_rfn;B=g_wpn;S=g_sim1;} else {A=g_imgn;B=g_pcn;S=g_sim2;}
  __shared__ float As[64][65], Bs[64][65];
  int t=threadIdx.x, tx=t&15, ty=t>>4;
  int m0=blockIdx.x*64, n0=blockIdx.y*64;
  #pragma unroll
  for(int i=0;i<16;i++){int idx=t+i*256,r=idx>>6,c=idx&63;
    As[r][c]=A[(m0+r)*CC+c]; Bs[r][c]=B[(n0+r)*CC+c];}
  __syncthreads();
  float acc[4][4];
  #pragma unroll
  for(int i=0;i<4;i++)
    #pragma unroll
    for(int j=0;j<4;j++) acc[i][j]=0.f;
  #pragma unroll 8
  for(int k=0;k<64;k++){
    float a[4],b[4];
    #pragma unroll
    for(int i=0;i<4;i++){a[i]=As[ty*4+i][k]; b[i]=Bs[tx*4+i][k];}
    #pragma unroll
    for(int i=0;i<4;i++)
      #pragma unroll
      for(int j=0;j<4;j++) acc[i][j]+=a[i]*b[j];
  }
  #pragma unroll
  for(int i=0;i<4;i++)
    #pragma unroll
    for(int j=0;j<4;j++) S[(m0+ty*4+i)*NN+n0+tx*4+j]=acc[i][j];
}

// merged colmax (blocks 0..7, coalesced) + rowmax (blocks 8..135)
__global__ __launch_bounds__(256) void cmrm_kernel(int sel){
  const float* S=sel?g_sim2:g_sim1;
  float* ic=sel?g_invc2:g_invc1;
  float* ir=sel?g_invr2:g_invr1;
  int b=blockIdx.x, t=threadIdx.x;
  if(b<8){
    __shared__ float sh[8][33];
    int ln=t&31, mr=t>>5, n=b*32+ln;
    float mx=-1e30f;
    for(int m=mr;m<MM;m+=8) mx=fmaxf(mx,S[m*NN+n]);
    sh[mr][ln]=mx;
    __syncthreads();
    if(t<32){
      float v=sh[0][t];
      #pragma unroll
      for(int i=1;i<8;i++) v=fmaxf(v,sh[i][t]);
      ic[b*32+t]=1.f/(v+1e-6f);
    }
  } else {
    int w=t>>5,l=t&31,m=(b-8)*8+w;
    float mx=-1e30f;
    for(int n=l;n<NN;n+=32) mx=fmaxf(mx,S[m*NN+n]);
    for(int o=16;o;o>>=1) mx=fmaxf(mx,__shfl_down_sync(~0u,mx,o));
    if(l==0) ir[m]=1.f/(mx+1e-10f);
  }
}

__global__ void knn_kernel(){
  int n=blockIdx.x,t=threadIdx.x;
  __shared__ float sx[NN*3], d2[NN], wm[8];
  __shared__ int wi[8];
  for(int i=t;i<NN*3;i+=256) sx[i]=g_xyz[i];
  __syncthreads();
  float cx=sx[n*3],cy=sx[n*3+1],cz=sx[n*3+2];
  float dx=sx[t*3]-cx,dy=sx[t*3+1]-cy,dz=sx[t*3+2]-cz;
  d2[t]=dx*dx+dy*dy+dz*dz;
  __syncthreads();
  for(int it=0;it<KK;it++){
    float v=d2[t]; int id=t;
    for(int o=16;o;o>>=1){
      float ov=__shfl_down_sync(~0u,v,o); int oi=__shfl_down_sync(~0u,id,o);
      if(ov<v||(ov==v&&oi<id)){v=ov;id=oi;}
    }
    if((t&31)==0){wm[t>>5]=v;wi[t>>5]=id;}
    __syncthreads();
    if(t==0){
      float bv=wm[0];int bi=wi[0];
      for(int w=1;w<8;w++) if(wm[w]<bv||(wm[w]==bv&&wi[w]<bi)){bv=wm[w];bi=wi[w];}
      g_knn[n*KK+it]=bi; d2[bi]=1e38f;
    }
    __syncthreads();
  }
}

#define MLP2_SMEM (15888*4)
__global__ __launch_bounds__(256) void mlp2_kernel(const float* __restrict__ wp,
    const float* __restrict__ w0,const float* __restrict__ b0,
    const float* __restrict__ w1,const float* __restrict__ b1,
    const float* __restrict__ w2,const float* __restrict__ b2){
  extern __shared__ float sm[];
  float* W0=sm; float* W1=W0+4352; float* W2=W1+4096;
  float* B0=W2+4096; float* B1=B0+64; float* B2=B1+64;
  float* IN=B2+64; float* Ha=IN+1088; float* Hb=Ha+1024; float* wk=Hb+1024;
  int n=blockIdx.x,t=threadIdx.x;
  for(int i=t;i<4352;i+=256) W0[i]=w0[i];
  for(int i=t;i<4096;i+=256){W1[i]=w1[i];W2[i]=w2[i];}
  if(t<64){B0[t]=b0[t];B1[t]=b1[t];B2[t]=b2[t];}
  for(int i=t;i<16*68;i+=256){
    int k=i/68,f=i%68,nb=g_knn[n*KK+k]; float val;
    if(f<64) val=wp[nb*CC+f];
    else if(f<67) val=g_xyz[nb*3+(f-64)]-g_xyz[n*3+(f-64)];
    else{
      float dx=g_xyz[nb*3]-g_xyz[n*3],dy=g_xyz[nb*3+1]-g_xyz[n*3+1],dz=g_xyz[nb*3+2]-g_xyz[n*3+2];
      val=sqrtf(dx*dx+dy*dy+dz*dz);
    }
    IN[k*68+f]=val;
  }
  __syncthreads();
  for(int o=t;o<1024;o+=256){int k=o>>6,j=o&63; float s=B0[j];
    #pragma unroll 4
    for(int i=0;i<68;i++) s+=IN[k*68+i]*W0[i*64+j];
    Ha[o]=fmaxf(s,0.f);}
  __syncthreads();
  for(int o=t;o<1024;o+=256){int k=o>>6,j=o&63; float s=B1[j];
    #pragma unroll 4
    for(int i=0;i<64;i++) s+=Ha[k*64+i]*W1[i*64+j];
    Hb[o]=fmaxf(s,0.f);}
  __syncthreads();
  for(int o=t;o<1024;o+=256){int k=o>>6,j=o&63; float s=B2[j];
    #pragma unroll 4
    for(int i=0;i<64;i++) s+=Hb[k*64+i]*W2[i*64+j];
    Ha[o]=fmaxf(s,0.f);}
  __syncthreads();
  if(t<16){float mx=-1e30f; for(int j=0;j<64;j++) mx=fmaxf(mx,Ha[t*64+j]); wk[t]=mx;}
  __syncthreads();
  if(t==0){
    float mx=-1e30f; for(int k=0;k<16;k++) mx=fmaxf(mx,wk[k]);
    float s=0.f; for(int k=0;k<16;k++){wk[k]=expf(wk[k]-mx);s+=wk[k];}
    float inv=1.f/s; for(int k=0;k<16;k++) wk[k]*=inv;
  }
  __syncthreads();
  float pf=0.f;
  if(t<64){ for(int k=0;k<16;k++) pf+=wk[k]*IN[k*68+t]; Hb[t]=pf; }
  __syncthreads();
  if(t<64){
    float ss=pf*pf;
    for(int o=16;o;o>>=1) ss+=__shfl_down_sync(~0u,ss,o);
    if((t&31)==0) wk[t>>5]=ss;
  }
  __syncthreads();
  if(t<64){
    float nrm=fmaxf(sqrtf(wk[0]+wk[1]),1e-12f);
    g_pcn[n*CC+t]=Hb[t]/nrm;
  }
}

#define MLP3_SMEM (14443*4)
__global__ __launch_bounds__(256) void mlp3_kernel(
    const float* __restrict__ w0,const float* __restrict__ b0,
    const float* __restrict__ w1,const float* __restrict__ b1,
    const float* __restrict__ w2,const float* __restrict__ b2){
  extern __shared__ float sm[];
  float* W0=sm; float* W1=W0+4288; float* W2=W1+4096;
  float* B0=W2+4096; float* B1=B0+64; float* B2=B1+64;
  float* IN=B2+64; float* Ha=IN+603; float* Hb=Ha+576; float* wk=Hb+576;
  int m=blockIdx.x,t=threadIdx.x,y=m>>5,x=m&31;
  for(int i=t;i<4288;i+=256) W0[i]=w0[i];
  for(int i=t;i<4096;i+=256){W1[i]=w1[i];W2[i]=w2[i];}
  if(t<64){B0[t]=b0[t];B1[t]=b1[t];B2[t]=b2[t];}
  for(int i=t;i<9*67;i+=256){
    int k=i/67,f=i%67,dy=k/3-1,dx=k%3-1,yy=y+dy,xx=x+dx;
    float val=0.f;
    if(yy>=0&&yy<32&&xx>=0&&xx<32){int mm=yy*32+xx; val=(f<3)?g_rfi[mm*3+f]:g_rf[mm*CC+f-3];}
    IN[k*67+f]=val;
  }
  __syncthreads();
  for(int o=t;o<576;o+=256){int k=o>>6,j=o&63; float s=B0[j];
    #pragma unroll 4
    for(int i=0;i<67;i++) s+=IN[k*67+i]*W0[i*64+j];
    Ha[o]=fmaxf(s,0.f);}
  __syncthreads();
  for(int o=t;o<576;o+=256){int k=o>>6,j=o&63; float s=B1[j];
    #pragma unroll 4
    for(int i=0;i<64;i++) s+=Ha[k*64+i]*W1[i*64+j];
    Hb[o]=fmaxf(s,0.f);}
  __syncthreads();
  for(int o=t;o<576;o+=256){int k=o>>6,j=o&63; float s=B2[j];
    #pragma unroll 4
    for(int i=0;i<64;i++) s+=Hb[k*64+i]*W2[i*64+j];
    Ha[o]=fmaxf(s,0.f);}
  __syncthreads();
  if(t<9){float mx=-1e30f; for(int j=0;j<64;j++) mx=fmaxf(mx,Ha[t*64+j]); wk[t]=mx;}
  __syncthreads();
  if(t==0){
    float mx=-1e30f; for(int k=0;k<9;k++) mx=fmaxf(mx,wk[k]);
    float s=0.f; for(int k=0;k<9;k++){wk[k]=expf(wk[k]-mx);s+=wk[k];}
    float inv=1.f/s; for(int k=0;k<9;k++) wk[k]*=inv;
  }
  __syncthreads();
  float pf=0.f;
  if(t<64){ for(int k=0;k<9;k++) pf+=wk[k]*IN[k*67+3+t]; Hb[t]=pf; }
  __syncthreads();
  if(t<64){
    float ss=pf*pf;
    for(int o=16;o;o>>=1) ss+=__shfl_down_sync(~0u,ss,o);
    if((t&31)==0) wk[t>>5]=ss;
  }
  __syncthreads();
  if(t<64){
    float nrm=fmaxf(sqrtf(wk[0]+wk[1]),1e-12f);
    g_imgn[m*CC+t]=Hb[t]/nrm;
  }
}

__global__ __launch_bounds__(256) void pack_kernel(){
  __shared__ float s1[32][33], s2[32][33];
  int m0=blockIdx.x*32, n0=blockIdx.y*32, t=threadIdx.x;
  #pragma unroll
  for(int i=0;i<4;i++){
    int idx=t+i*256, mr=idx>>5, nc=idx&31;
    s1[mr][nc]=g_sim1[(m0+mr)*NN+n0+nc];
    s2[mr][nc]=g_sim2[(m0+mr)*NN+n0+nc];
  }
  __syncthreads();
  #pragma unroll
  for(int i=0;i<4;i++){
    int idx=t+i*256, nr=idx>>5, mc=idx&31;
    int n=n0+nr, m=m0+mc;
    float v1=s1[mc][nr], v2=s2[mc][nr];
    float4 q; q.x=v1*g_invc1[n]; q.y=v1*g_invr1[m]; q.z=v2*g_invc2[n]; q.w=v2*g_invr2[m];
    g_simQ[n*MM+m]=q;
  }
}

// merged basem (blocks 0..MM-1) + basen (blocks MM..MM+NN-1)
__global__ void basemn_kernel(const float* __restrict__ wp,
                              const float* __restrict__ w1_0,const float* __restrict__ b1_0){
  int b=blockIdx.x,t=threadIdx.x;
  __shared__ float in[67];
  if(b<MM){
    int m=b;
    if(t<3) in[t]=g_rfi[m*3+t]; else if(t<67) in[t]=g_rf[m*CC+t-3];
    __syncthreads();
    float acc=b1_0[t];
    #pragma unroll
    for(int i=0;i<3;i++) acc+=in[i]*w1_0[(3+i)*128+t];
    #pragma unroll 4
    for(int i=0;i<64;i++) acc+=in[3+i]*w1_0[(70+i)*128+t];
    g_basem[m*128+t]=acc;
  } else {
    int n=b-MM;
    if(t<3) in[t]=g_xyz[n*3+t]; else if(t<67) in[t]=wp[n*CC+t-3];
    __syncthreads();
    float acc=0.f;
    #pragma unroll
    for(int i=0;i<3;i++) acc+=in[i]*w1_0[i*128+t];
    #pragma unroll 4
    for(int i=0;i<64;i++) acc+=in[3+i]*w1_0[(6+i)*128+t];
    g_basen[n*128+t]=acc;
  }
}

// =============== big kernel: mma.sync bf16 hi/lo ===============
#define SB_A1H 0
#define SB_A1L 16384
#define SB_A2H 32768
#define SB_A2L 40960
#define SB_W1H 49152
#define SB_W1L 65536
#define SB_W2H 81920
#define SB_W2L 90112
#define SB_WS  98304
#define SB_BN  100352
#define SB_BA  100864
#define SB_BB  101120
#define SB_SQ  101376
#define SB_RM  102400
#define SB_EE  102656
#define SB_SC  102912
#define SB_AS  103936
#define SB_CO  104192
#define SB_MS  104208
#define SB_AL  104212
#define SB_ZS  104216
#define SB_RMP 104224
#define BIG_SMEM 104800

__device__ __forceinline__ unsigned smem_u32(const void* p){
  unsigned a;
  asm("{ .reg .u64 tmp; cvta.to.shared.u64 tmp, %1; cvt.u32.u64 %0, tmp; }":"=r"(a):"l"(p));
  return a;
}
#define LDM4(r0,r1,r2,r3,addr) \
  asm volatile("ldmatrix.sync.aligned.m8n8.x4.shared.b16 {%0,%1,%2,%3},[%4];" \
    : "=r"(r0),"=r"(r1),"=r"(r2),"=r"(r3) : "r"(addr))
#define MMA16816(d,a0,a1,a2,a3,b0,b1) \
  asm volatile("mma.sync.aligned.m16n8k16.row.col.f32.bf16.bf16.f32 " \
    "{%0,%1,%2,%3},{%4,%5,%6,%7},{%8,%9},{%0,%1,%2,%3};" \
    : "+f"((d)[0]),"+f"((d)[1]),"+f"((d)[2]),"+f"((d)[3]) \
    : "r"(a0),"r"(a1),"r"(a2),"r"(a3),"r"(b0),"r"(b1))

__global__ __launch_bounds__(256,2) void big_kernel(
    const float* __restrict__ w1_0,const float* __restrict__ b1_1,const float* __restrict__ b1_2){
  extern __shared__ char smc[];
  unsigned sb=smem_u32(smc);
  int t=threadIdx.x, n=blockIdx.x;
  int wid=t>>5, lane=t&31;
  int mg=wid&3, ng=wid>>2;
  float* WS=(float*)(smc+SB_WS);
  float* BN=(float*)(smc+SB_BN);
  float* BA=(float*)(smc+SB_BA);
  float* BB=(float*)(smc+SB_BB);
  float4* SQ=(float4*)(smc+SB_SQ);
  float* RM=(float*)(smc+SB_RM);
  float* EE=(float*)(smc+SB_EE);
  float* SC=(float*)(smc+SB_SC);
  float* AS=(float*)(smc+SB_AS);
  float* CO=(float*)(smc+SB_CO);
  float* MS=(float*)(smc+SB_MS);
  float* AL=(float*)(smc+SB_AL);
  float* ZS=(float*)(smc+SB_ZS);
  float* RMP=(float*)(smc+SB_RMP);
  float* FS=(float*)(smc+SB_A1H);

  {
    uint4* d1=(uint4*)(smc+SB_W1H); const uint4* s1=(const uint4*)g_W1h;
    uint4* d2=(uint4*)(smc+SB_W1L); const uint4* s2=(const uint4*)g_W1l;
    for(int i=t;i<1024;i+=256){ d1[i]=s1[i]; d2[i]=s2[i]; }
    uint4* d3=(uint4*)(smc+SB_W2H); const uint4* s3=(const uint4*)g_W2h;
    uint4* d4=(uint4*)(smc+SB_W2L); const uint4* s4=(const uint4*)g_W2l;
    for(int i=t;i<512;i+=256){ d3[i]=s3[i]; d4[i]=s4[i]; }
  }
  for(int i=t;i<512;i+=256) WS[i]=w1_0[134*128+i];
  if(t<128) BN[t]=g_basen[n*128+t];
  if(t<64){ BA[t]=b1_1[t]; BB[t]=b1_2[t]; AS[t]=0.f; }
  if(t<4) CO[t]=0.f;
  if(t==0){ ZS[0]=0.f; MS[0]=-1e30f; }
  __syncthreads();

  int arow = mg*16 + (lane&15);
  unsigned axor = ((unsigned)(arow&7))<<4;
  int bg = lane>>3;
  int brow = ng*32 + (lane&7) + (bg&1)*8;
  unsigned bxor = ((unsigned)(brow&7))<<4;
  unsigned akadd = ((unsigned)(lane>>4))*16u;
  unsigned bkadd = ((unsigned)(bg>>1))*16u;
  int erow = mg*16 + (lane>>2);
  int ecol0 = (lane&3)*2;

  int c_ = t&127, half_=t>>7;

  for(int tile=0;tile<16;tile++){
    int m0=tile*64;
    if(t<64) SQ[t]=g_simQ[n*MM+m0+t];
    __syncthreads();
    // phase A
    #pragma unroll 4
    for(int i=0;i<32;i++){
      int r=half_*32+i;
      float4 q=SQ[r];
      float h=g_basem[(m0+r)*128+c_]+BN[c_]
             +q.x*WS[c_]+q.y*WS[128+c_]+q.z*WS[256+c_]+q.w*WS[384+c_];
      h=fmaxf(h,0.f);
      __nv_bfloat16 hi=__float2bfloat16(h);
      float lo=h-__bfloat162float(hi);
      unsigned o=swz128(r,c_);
      *(__nv_bfloat16*)(smc+SB_A1H+o)=hi;
      *(__nv_bfloat16*)(smc+SB_A1L+o)=__float2bfloat16(lo);
    }
    __syncthreads();
    // layer 1
    float d1[4][4];
    #pragma unroll
    for(int j=0;j<4;j++){d1[j][0]=0;d1[j][1]=0;d1[j][2]=0;d1[j][3]=0;}
    #pragma unroll
    for(int ks=0;ks<8;ks++){
      unsigned ak2=ks*32u+akadd, bk2=ks*32u+bkadd;
      unsigned ah0,ah1,ah2,ah3, al0,al1,al2,al3;
      LDM4(ah0,ah1,ah2,ah3, sb+SB_A1H+(unsigned)arow*256u+(ak2^axor));
      LDM4(al0,al1,al2,al3, sb+SB_A1L+(unsigned)arow*256u+(ak2^axor));
      unsigned bh0,bh1,bh2,bh3, bh4,bh5,bh6,bh7;
      unsigned bl0,bl1,bl2,bl3, bl4,bl5,bl6,bl7;
      unsigned boff1=(unsigned)brow*256u+(bk2^bxor);
      unsigned boff2=(unsigned)(brow+16)*256u+(bk2^bxor);
      LDM4(bh0,bh1,bh2,bh3, sb+SB_W1H+boff1);
      LDM4(bh4,bh5,bh6,bh7, sb+SB_W1H+boff2);
      LDM4(bl0,bl1,bl2,bl3, sb+SB_W1L+boff1);
      LDM4(bl4,bl5,bl6,bl7, sb+SB_W1L+boff2);
      MMA16816(d1[0],ah0,ah1,ah2,ah3,bh0,bh2);
      MMA16816(d1[1],ah0,ah1,ah2,ah3,bh1,bh3);
      MMA16816(d1[2],ah0,ah1,ah2,ah3,bh4,bh6);
      MMA16816(d1[3],ah0,ah1,ah2,ah3,bh5,bh7);
      MMA16816(d1[0],ah0,ah1,ah2,ah3,bl0,bl2);
      MMA16816(d1[1],ah0,ah1,ah2,ah3,bl1,bl3);
      MMA16816(d1[2],ah0,ah1,ah2,ah3,bl4,bl6);
      MMA16816(d1[3],ah0,ah1,ah2,ah3,bl5,bl7);
      MMA16816(d1[0],al0,al1,al2,al3,bh0,bh2);
      MMA16816(d1[1],al0,al1,al2,al3,bh1,bh3);
      MMA16816(d1[2],al0,al1,al2,al3,bh4,bh6);
      MMA16816(d1[3],al0,al1,al2,al3,bh5,bh7);
    }
    // epilogue 1
    #pragma unroll
    for(int j=0;j<4;j++){
      int cj=ng*32+j*8+ecol0;
      float b0=BA[cj], b1=BA[cj+1];
      float v00=fmaxf(d1[j][0]+b0,0.f), v01=fmaxf(d1[j][1]+b1,0.f);
      float v10=fmaxf(d1[j][2]+b0,0.f), v11=fmaxf(d1[j][3]+b1,0.f);
      __nv_bfloat162 h0, h1, l0, l1;
      h0.x=__float2bfloat16(v00); h0.y=__float2bfloat16(v01);
      h1.x=__float2bfloat16(v10); h1.y=__float2bfloat16(v11);
      l0.x=__float2bfloat16(v00-__bfloat162float(h0.x)); l0.y=__float2bfloat16(v01-__bfloat162float(h0.y));
      l1.x=__float2bfloat16(v10-__bfloat162float(h1.x)); l1.y=__float2bfloat16(v11-__bfloat162float(h1.y));
      unsigned o1=swz64(erow,cj), o2=swz64(erow+8,cj);
      *(__nv_bfloat162*)(smc+SB_A2H+o1)=h0;
      *(__nv_bfloat162*)(smc+SB_A2H+o2)=h1;
      *(__nv_bfloat162*)(smc+SB_A2L+o1)=l0;
      *(__nv_bfloat162*)(smc+SB_A2L+o2)=l1;
    }
    __syncthreads();
    // layer 2
    float d2[4][4];
    #pragma unroll
    for(int j=0;j<4;j++){d2[j][0]=0;d2[j][1]=0;d2[j][2]=0;d2[j][3]=0;}
    #pragma unroll
    for(int ks=0;ks<4;ks++){
      unsigned ak2=ks*32u+akadd, bk2=ks*32u+bkadd;
      unsigned ah0,ah1,ah2,ah3, al0,al1,al2,al3;
      LDM4(ah0,ah1,ah2,ah3, sb+SB_A2H+(unsigned)arow*128u+(ak2^axor));
      LDM4(al0,al1,al2,al3, sb+SB_A2L+(unsigned)arow*128u+(ak2^axor));
      unsigned bh0,bh1,bh2,bh3, bh4,bh5,bh6,bh7;
      unsigned bl0,bl1,bl2,bl3, bl4,bl5,bl6,bl7;
      unsigned boff1=(unsigned)brow*128u+(bk2^bxor);
      unsigned boff2=(unsigned)(brow+16)*128u+(bk2^bxor);
      LDM4(bh0,bh1,bh2,bh3, sb+SB_W2H+boff1);
      LDM4(bh4,bh5,bh6,bh7, sb+SB_W2H+boff2);
      LDM4(bl0,bl1,bl2,bl3, sb+SB_W2L+boff1);
      LDM4(bl4,bl5,bl6,bl7, sb+SB_W2L+boff2);
      MMA16816(d2[0],ah0,ah1,ah2,ah3,bh0,bh2);
      MMA16816(d2[1],ah0,ah1,ah2,ah3,bh1,bh3);
      MMA16816(d2[2],ah0,ah1,ah2,ah3,bh4,bh6);
      MMA16816(d2[3],ah0,ah1,ah2,ah3,bh5,bh7);
      MMA16816(d2[0],ah0,ah1,ah2,ah3,bl0,bl2);
      MMA16816(d2[1],ah0,ah1,ah2,ah3,bl1,bl3);
      MMA16816(d2[2],ah0,ah1,ah2,ah3,bl4,bl6);
      MMA16816(d2[3],ah0,ah1,ah2,ah3,bl5,bl7);
      MMA16816(d2[0],al0,al1,al2,al3,bh0,bh2);
      MMA16816(d2[1],al0,al1,al2,al3,bh1,bh3);
      MMA16816(d2[2],al0,al1,al2,al3,bh4,bh6);
      MMA16816(d2[3],al0,al1,al2,al3,bh5,bh7);
    }
    __syncthreads();
    // epilogue 2: F -> FS + fragment rowmax
    float v0=-1e30f, v1=-1e30f;
    #pragma unroll
    for(int j=0;j<4;j++){
      int cj=ng*32+j*8+ecol0;
      float f00=fmaxf(d2[j][0]+BB[cj],0.f);
      float f01=fmaxf(d2[j][1]+BB[cj+1],0.f);
      float f10=fmaxf(d2[j][2]+BB[cj],0.f);
      float f11=fmaxf(d2[j][3]+BB[cj+1],0.f);
      FS[erow*68+cj]=f00; FS[erow*68+cj+1]=f01;
      FS[(erow+8)*68+cj]=f10; FS[(erow+8)*68+cj+1]=f11;
      v0=fmaxf(v0,fmaxf(f00,f01));
      v1=fmaxf(v1,fmaxf(f10,f11));
    }
    v0=fmaxf(v0,__shfl_xor_sync(~0u,v0,1)); v0=fmaxf(v0,__shfl_xor_sync(~0u,v0,2));
    v1=fmaxf(v1,__shfl_xor_sync(~0u,v1,1)); v1=fmaxf(v1,__shfl_xor_sync(~0u,v1,2));
    if((lane&3)==0){ RMP[erow*2+ng]=v0; RMP[(erow+8)*2+ng]=v1; }
    __syncthreads();
    if(t<64) RM[t]=fmaxf(RMP[2*t],RMP[2*t+1]);
    __syncthreads();
    if(t<32){
      float v=fmaxf(RM[t],RM[t+32]);
      for(int o=16;o;o>>=1) v=fmaxf(v,__shfl_down_sync(~0u,v,o));
      if(t==0){ float oldM=MS[0], nM=fmaxf(oldM,v); AL[0]=expf(oldM-nM); MS[0]=nM; }
    }
    __syncthreads();
    if(t<64) EE[t]=expf(RM[t]-MS[0]);
    __syncthreads();
    {
      int c=t&63, q=t>>6;
      float s=0.f;
      #pragma unroll 4
      for(int r=q*16;r<q*16+16;r++) s+=EE[r]*FS[r*68+c];
      SC[t]=s;
    }
    __syncthreads();
    float alpha=AL[0];
    if(t<64) AS[t]=AS[t]*alpha+SC[t]+SC[64+t]+SC[128+t]+SC[192+t];
    else if(t<96){
      int l=t&31; float a=0.f;
      for(int r=l;r<64;r+=32) a+=EE[r]*g_rfi[(m0+r)*3+0];
      for(int o=16;o;o>>=1) a+=__shfl_down_sync(~0u,a,o);
      if(l==0) CO[0]=CO[0]*alpha+a;
    } else if(t<128){
      int l=t&31; float a=0.f;
      for(int r=l;r<64;r+=32) a+=EE[r]*g_rfi[(m0+r)*3+1];
      for(int o=16;o;o>>=1) a+=__shfl_down_sync(~0u,a,o);
      if(l==0) CO[1]=CO[1]*alpha+a;
    } else if(t<160){
      int l=t&31; float a=0.f;
      for(int r=l;r<64;r+=32) a+=EE[r]*g_rfi[(m0+r)*3+2];
      for(int o=16;o;o>>=1) a+=__shfl_down_sync(~0u,a,o);
      if(l==0) CO[2]=CO[2]*alpha+a;
    } else if(t<192){
      int l=t&31; float z=0.f;
      for(int r=l;r<64;r+=32) z+=EE[r];
      for(int o=16;o;o>>=1) z+=__shfl_down_sync(~0u,z,o);
      if(l==0) ZS[0]=ZS[0]*alpha+z;
    }
    __syncthreads();
  }
  if(t<64) g_att[n*CC+t]=AS[t]/ZS[0];
  else if(t<67) g_corres[n*3+(t-64)]=CO[t-64]/ZS[0];
}

__global__ void head_kernel(const float* __restrict__ wm0,const float* __restrict__ bm0,
    const float* __restrict__ wm1,const float* __restrict__ bm1,
    const float* __restrict__ wm2,const float* __restrict__ bm2,float* __restrict__ outw){
  int n=blockIdx.x,t=threadIdx.x;
  __shared__ float a[64],h1[64],h2[128];
  if(t<64) a[t]=g_att[n*CC+t];
  __syncthreads();
  if(t<64){
    float s=bm0[t];
    #pragma unroll 4
    for(int k=0;k<64;k++) s+=a[k]*wm0[k*64+t];
    h1[t]=fmaxf(s,0.f);
  }
  __syncthreads();
  {
    float s=bm1[t];
    #pragma unroll 4
    for(int k=0;k<64;k++) s+=h1[k]*wm1[k*128+t];
    h2[t]=fmaxf(s,0.f);
  }
  __syncthreads();
  if(t==0){
    float l0=bm2[0],l1=bm2[1];
    for(int k=0;k<128;k++){l0+=h2[k]*wm2[k*2];l1+=h2[k]*wm2[k*2+1];}
    float mx=fmaxf(l0,l1),e0=expf(l0-mx),e1=expf(l1-mx),inv=1.f/(e0+e1);
    outw[n*2]=e0*inv; outw[n*2+1]=e1*inv;
    g_win[n]=(l1>l0)?1.f:0.f;
  }
}

__device__ float brs(float v,float* red){
  int t=threadIdx.x;
  red[t]=v; __syncthreads();
  for(int s=128;s>0;s>>=1){ if(t<s) red[t]+=red[t+s]; __syncthreads(); }
  float r=red[0]; __syncthreads();
  return r;
}

__global__ void pnp_kernel(float* __restrict__ out){
  __shared__ float red[256];
  int t=threadIdx.x;
  float w=g_win[t];
  float sx=g_xyz[t*3],sy=g_xyz[t*3+1],sz=g_xyz[t*3+2];
  float u=g_corres[t*3],v=g_corres[t*3+1];
  float dx=u*sz,dy=v*sz,dz=sz;
  float sw=brs(w,red);
  float wn=w/(sw+1e-8f);
  float scx=brs(wn*sx,red),scy=brs(wn*sy,red),scz=brs(wn*sz,red);
  float dcx=brs(wn*dx,red),dcy=brs(wn*dy,red),dcz=brs(wn*dz,red);
  float ax=sx-scx,ay=sy-scy,az=sz-scz;
  float bx=dx-dcx,by=dy-dcy,bz=dz-dcz;
  float hm[9];
  hm[0]=brs(wn*ax*bx,red);hm[1]=brs(wn*ax*by,red);hm[2]=brs(wn*ax*bz,red);
  hm[3]=brs(wn*ay*bx,red);hm[4]=brs(wn*ay*by,red);hm[5]=brs(wn*ay*bz,red);
  hm[6]=brs(wn*az*bx,red);hm[7]=brs(wn*az*by,red);hm[8]=brs(wn*az*bz,red);
  if(t==0){
    double h[3][3]={{hm[0],hm[1],hm[2]},{hm[3],hm[4],hm[5]},{hm[6],hm[7],hm[8]}};
    double A[3][3],V[3][3]={{1,0,0},{0,1,0},{0,0,1}};
    for(int i=0;i<3;i++)for(int j=0;j<3;j++){double s=0;for(int k=0;k<3;k++)s+=h[k][i]*h[k][j];A[i][j]=s;}
    const int P[3]={0,0,1},Q[3]={1,2,2};
    for(int sweep=0;sweep<20;sweep++)
      for(int r=0;r<3;r++){
        int p=P[r],qq=Q[r];
        double apq=A[p][qq];
        if(fabs(apq)<1e-300) continue;
        double tau=(A[qq][qq]-A[p][p])/(2.0*apq);
        double tt=((tau>=0)?1.0:-1.0)/(fabs(tau)+sqrt(1.0+tau*tau));
        double c=1.0/sqrt(1.0+tt*tt),s=tt*c;
        for(int k=0;k<3;k++){double a1=A[k][p],a2=A[k][qq];A[k][p]=c*a1-s*a2;A[k][qq]=s*a1+c*a2;}
        for(int k=0;k<3;k++){double a1=A[p][k],a2=A[qq][k];A[p][k]=c*a1-s*a2;A[qq][k]=s*a1+c*a2;}
        for(int k=0;k<3;k++){double v1=V[k][p],v2=V[k][qq];V[k][p]=c*v1-s*v2;V[k][qq]=s*v1+c*v2;}
      }
    double lam[3]={A[0][0],A[1][1],A[2][2]};
    int o[3]={0,1,2};
    if(lam[o[0]]<lam[o[1]]){int x=o[0];o[0]=o[1];o[1]=x;}
    if(lam[o[1]]<lam[o[2]]){int x=o[1];o[1]=o[2];o[2]=x;}
    if(lam[o[0]]<lam[o[1]]){int x=o[0];o[0]=o[1];o[1]=x;}
    double vv[3][3],uu[3][3],sg[3];
    for(int i=0;i<3;i++){
      sg[i]=sqrt(fmax(lam[o[i]],0.0));
      for(int k=0;k<3;k++) vv[i][k]=V[k][o[i]];
    }
    for(int i=0;i<2;i++){
      for(int j=0;j<3;j++){double s=0;for(int k=0;k<3;k++)s+=h[j][k]*vv[i][k];uu[i][j]=s/fmax(sg[i],1e-300);}
    }
    if(sg[2]>1e-9*sg[0]){
      for(int j=0;j<3;j++){double s=0;for(int k=0;k<3;k++)s+=h[j][k]*vv[2][k];uu[2][j]=s/sg[2];}
    } else {
      uu[2][0]=uu[0][1]*uu[1][2]-uu[0][2]*uu[1][1];
      uu[2][1]=uu[0][2]*uu[1][0]-uu[0][0]*uu[1][2];
      uu[2][2]=uu[0][0]*uu[1][1]-uu[0][1]*uu[1][0];
    }
    double detV=vv[0][0]*(vv[1][1]*vv[2][2]-vv[1][2]*vv[2][1])
               -vv[0][1]*(vv[1][0]*vv[2][2]-vv[1][2]*vv[2][0])
               +vv[0][2]*(vv[1][0]*vv[2][1]-vv[1][1]*vv[2][0]);
    double detU=uu[0][0]*(uu[1][1]*uu[2][2]-uu[1][2]*uu[2][1])
               -uu[0][1]*(uu[1][0]*uu[2][2]-uu[1][2]*uu[2][0])
               +uu[0][2]*(uu[1][0]*uu[2][1]-uu[1][1]*uu[2][0]);
    double d=detV*detU;
    double R[3][3];
    for(int i=0;i<3;i++)for(int j=0;j<3;j++)
      R[i][j]=vv[0][i]*uu[0][j]+vv[1][i]*uu[1][j]+d*vv[2][i]*uu[2][j];
    double sc[3]={scx,scy,scz},dc[3]={dcx,dcy,dcz};
    for(int i=0;i<3;i++){
      for(int j=0;j<3;j++) out[i*3+j]=(float)R[i][j];
      double s=0; for(int j=0;j<3;j++) s+=R[i][j]*sc[j];
      out[9+i]=(float)(dc[i]-s);
    }
  }
}

extern "C" void kernel_launch(void* const* d_in, const int* in_sizes, int n_in,
                              void* d_out, int out_size){
  const float* wx  =(const float*)d_in[0];
  const float* wp  =(const float*)d_in[1];
  const float* RF3 =(const float*)d_in[2];
  const float* RF3i=(const float*)d_in[3];
  const float* lz  =(const float*)d_in[4];
  const float* w2_0=(const float*)d_in[5];  const float* b2_0=(const float*)d_in[6];
  const float* w2_1=(const float*)d_in[7];  const float* b2_1=(const float*)d_in[8];
  const float* w2_2=(const float*)d_in[9];  const float* b2_2=(const float*)d_in[10];
  const float* w3_0=(const float*)d_in[11]; const float* b3_0=(const float*)d_in[12];
  const float* w3_1=(const float*)d_in[13]; const float* b3_1=(const float*)d_in[14];
  const float* w3_2=(const float*)d_in[15]; const float* b3_2=(const float*)d_in[16];
  const float* w1_0=(const float*)d_in[17]; const float* b1_0=(const float*)d_in[18];
  const float* w1_1=(const float*)d_in[19]; const float* b1_1=(const float*)d_in[20];
  const float* w1_2=(const float*)d_in[21]; const float* b1_2=(const float*)d_in[22];
  const float* wm_0=(const float*)d_in[23]; const float* bm_0=(const float*)d_in[24];
  const float* wm_1=(const float*)d_in[25]; const float* bm_1=(const float*)d_in[26];
  const float* wm_2=(const float*)d_in[27]; const float* bm_2=(const float*)d_in[28];
  float* out=(float*)d_out;

  cudaFuncSetAttribute(mlp2_kernel, cudaFuncAttributeMaxDynamicSharedMemorySize, MLP2_SMEM);
  cudaFuncSetAttribute(mlp3_kernel, cudaFuncAttributeMaxDynamicSharedMemorySize, MLP3_SMEM);
  cudaFuncSetAttribute(big_kernel,  cudaFuncAttributeMaxDynamicSharedMemorySize, BIG_SMEM);

  prep_kernel<<<MM,64>>>(wx,lz,RF3,RF3i,wp);
  bprep_kernel<<<1,256>>>(w1_1,w1_2);
  corr_kernel<<<dim3(MM/64,NN/64),256>>>(0);
  cmrm_kernel<<<136,256>>>(0);
  knn_kernel<<<NN,256>>>();
  mlp2_kernel<<<NN,256,MLP2_SMEM>>>(wp,w2_0,b2_0,w2_1,b2_1,w2_2,b2_2);
  mlp3_kernel<<<MM,256,MLP3_SMEM>>>(w3_0,b3_0,w3_1,b3_1,w3_2,b3_2);
  corr_kernel<<<dim3(MM/64,NN/64),256>>>(1);
  cmrm_kernel<<<136,256>>>(1);
  pack_kernel<<<dim3(MM/32,NN/32),256>>>();
  basemn_kernel<<<MM+NN,128>>>(wp,w1_0,b1_0);
  big_kernel<<<NN,256,BIG_SMEM>>>(w1_0,b1_1,b1_2);
  head_kernel<<<NN,128>>>(wm_0,bm_0,wm_1,bm_1,wm_2,bm_2,out+12);
  pnp_kernel<<<1,NN>>>(out);
}